// round 2
// baseline (speedup 1.0000x reference)
#include <cuda_runtime.h>

// ---------------- problem constants ----------------
#define Bn   8
#define Sn   512
#define Ln   6
#define Dn   512
#define Hn   8
#define HDn  64
#define HIDn 2048
#define Cn   256
#define INDIM 257
#define Mn   (Bn * Sn)          // 4096 rows

#define OUT_LOGITS_PER_B 1020   // 2 * 510
#define OUT_FEAS_OFF     (Bn * OUT_LOGITS_PER_B)   // 8160

// ---------------- scratch (device globals; no allocation) ----------------
__device__ float g_x  [Mn * Dn];            // residual stream
__device__ float g_q  [Mn * Dn];
__device__ float g_k  [Mn * Dn];
__device__ float g_v  [Mn * Dn];
__device__ float g_att[Mn * Dn];            // attention output (pre O-proj)
__device__ float g_sc [(size_t)Bn * Hn * Sn * Sn];   // 64 MB scores
__device__ float g_h  [Mn * HIDn];          // FFN hidden

// ============================================================
// 1) Build x = class_proj(concat(embed[idx], nd))  per row
// ============================================================
__global__ void build_x_kernel(const float* __restrict__ sol,
                               const float* __restrict__ cap,
                               const float* __restrict__ emb,
                               const float* __restrict__ srcW, const float* __restrict__ srcB,
                               const float* __restrict__ candW, const float* __restrict__ candB,
                               const float* __restrict__ depW, const float* __restrict__ depB)
{
    int row = blockIdx.x;            // 0..4095
    int b = row / Sn, s = row % Sn;
    __shared__ float xin[INDIM];
    int t = threadIdx.x;             // 256 threads

    int idx = (int)sol[(size_t)row * 4 + 0];
    xin[t] = emb[(size_t)idx * Cn + t];
    if (t == 0) {
        float rem = sol[(size_t)(b * Sn) * 4 + 3];
        float nd = (s == 0) ? 0.0f
                            : 2.0f * (sol[(size_t)row * 4 + 2] - rem) / cap[b];
        xin[Cn] = nd;
    }
    __syncthreads();

    const float* W; const float* bb;
    if (s == 0)           { W = srcW;  bb = srcB;  }
    else if (s == Sn - 1) { W = depW;  bb = depB;  }
    else                  { W = candW; bb = candB; }

    int c = t;                       // two columns per thread: c, c+256
    float acc0 = bb[c], acc1 = bb[c + 256];
    #pragma unroll 4
    for (int k = 0; k < INDIM; k++) {
        float xv = xin[k];
        acc0 += xv * W[k * Dn + c];
        acc1 += xv * W[k * Dn + c + 256];
    }
    g_x[(size_t)row * Dn + c]       = acc0;
    g_x[(size_t)row * Dn + c + 256] = acc1;
}

// ============================================================
// 2) Generic GEMM: C[M,N] = A[M,K] @ B[K,N] + bias (+ Res, +ReLU)
//    BM=BN=64, BK=16, 256 threads, 4x4 micro-tile, float4 smem reads
// ============================================================
template<bool RELU, bool RES>
__global__ __launch_bounds__(256) void gemm_kernel(
    const float* __restrict__ A, const float* __restrict__ Bw,
    const float* __restrict__ bias, const float* __restrict__ Res,
    float* __restrict__ C, int K, int N)
{
    const int t  = threadIdx.x;
    const int tx = t & 15, ty = t >> 4;
    const int m0 = blockIdx.y * 64, n0 = blockIdx.x * 64;

    __shared__ float As[16][68];   // [k][m], pad 4 keeps float4 alignment
    __shared__ float Bs[16][64];   // [k][n]

    const int am  = t >> 2;            // 0..63 (row of A tile)
    const int ak4 = (t & 3) * 4;       // k offset (float4)
    const int bk  = t >> 4;            // 0..15 (k row of B tile)
    const int bn4 = (t & 15) * 4;      // n offset (float4)

    float acc[4][4] = {};

    for (int k0 = 0; k0 < K; k0 += 16) {
        float4 a4 = *(const float4*)&A[(size_t)(m0 + am) * K + k0 + ak4];
        As[ak4 + 0][am] = a4.x; As[ak4 + 1][am] = a4.y;
        As[ak4 + 2][am] = a4.z; As[ak4 + 3][am] = a4.w;
        *(float4*)&Bs[bk][bn4] =
            *(const float4*)&Bw[(size_t)(k0 + bk) * N + n0 + bn4];
        __syncthreads();
        #pragma unroll
        for (int kk = 0; kk < 16; kk++) {
            float4 av = *(const float4*)&As[kk][ty * 4];
            float4 bv = *(const float4*)&Bs[kk][tx * 4];
            float a[4] = {av.x, av.y, av.z, av.w};
            float b[4] = {bv.x, bv.y, bv.z, bv.w};
            #pragma unroll
            for (int i = 0; i < 4; i++)
                #pragma unroll
                for (int j = 0; j < 4; j++)
                    acc[i][j] += a[i] * b[j];
        }
        __syncthreads();
    }

    float4 bi = *(const float4*)&bias[n0 + tx * 4];
    float bvv[4] = {bi.x, bi.y, bi.z, bi.w};
    #pragma unroll
    for (int i = 0; i < 4; i++) {
        int m = m0 + ty * 4 + i;
        float4 o;
        float v0 = acc[i][0] + bvv[0];
        float v1 = acc[i][1] + bvv[1];
        float v2 = acc[i][2] + bvv[2];
        float v3 = acc[i][3] + bvv[3];
        if (RELU) { v0 = fmaxf(v0, 0.f); v1 = fmaxf(v1, 0.f);
                    v2 = fmaxf(v2, 0.f); v3 = fmaxf(v3, 0.f); }
        if (RES) {
            float4 r = *(const float4*)&Res[(size_t)m * N + n0 + tx * 4];
            v0 += r.x; v1 += r.y; v2 += r.z; v3 += r.w;
        }
        o.x = v0; o.y = v1; o.z = v2; o.w = v3;
        *(float4*)&C[(size_t)m * N + n0 + tx * 4] = o;
    }
}

// ============================================================
// 3) scores[bh, q, k] = 0.125 * sum_e Q[b,q,h,e] * K[b,k,h,e]
//    (constant +s*log(n) bias is softmax-invariant -> skipped)
// ============================================================
__global__ __launch_bounds__(256) void scores_kernel()
{
    int bh = blockIdx.z; int b = bh >> 3, h = bh & 7;
    int q0 = blockIdx.y * 64, k0 = blockIdx.x * 64;
    __shared__ float Qs[64][68];   // [e][q]
    __shared__ float Ks[64][68];   // [e][k]
    int t = threadIdx.x, tx = t & 15, ty = t >> 4;

    int r  = t >> 2;              // tile row 0..63
    int e0 = (t & 3) * 4;
    const float* Qp = g_q + ((size_t)(b * Sn + q0 + r)) * Dn + h * HDn;
    const float* Kp = g_k + ((size_t)(b * Sn + k0 + r)) * Dn + h * HDn;
    #pragma unroll
    for (int ee = 0; ee < 64; ee += 16) {
        float4 q4 = *(const float4*)&Qp[e0 + ee];
        Qs[e0 + ee + 0][r] = q4.x; Qs[e0 + ee + 1][r] = q4.y;
        Qs[e0 + ee + 2][r] = q4.z; Qs[e0 + ee + 3][r] = q4.w;
        float4 k4 = *(const float4*)&Kp[e0 + ee];
        Ks[e0 + ee + 0][r] = k4.x; Ks[e0 + ee + 1][r] = k4.y;
        Ks[e0 + ee + 2][r] = k4.z; Ks[e0 + ee + 3][r] = k4.w;
    }
    __syncthreads();

    float acc[4][4] = {};
    #pragma unroll
    for (int e = 0; e < 64; e++) {
        float4 av = *(const float4*)&Qs[e][ty * 4];
        float4 bv = *(const float4*)&Ks[e][tx * 4];
        float a[4] = {av.x, av.y, av.z, av.w};
        float b2[4] = {bv.x, bv.y, bv.z, bv.w};
        #pragma unroll
        for (int i = 0; i < 4; i++)
            #pragma unroll
            for (int j = 0; j < 4; j++)
                acc[i][j] += a[i] * b2[j];
    }
    float* Sp = g_sc + (size_t)bh * Sn * Sn;
    #pragma unroll
    for (int i = 0; i < 4; i++) {
        float4 o = make_float4(acc[i][0] * 0.125f, acc[i][1] * 0.125f,
                               acc[i][2] * 0.125f, acc[i][3] * 0.125f);
        *(float4*)&Sp[(size_t)(q0 + ty * 4 + i) * Sn + k0 + tx * 4] = o;
    }
}

// ============================================================
// 4) row softmax over the 512-wide score rows
// ============================================================
__global__ void softmax_kernel()
{
    size_t row = blockIdx.x;
    float* p = g_sc + row * Sn;
    int t = threadIdx.x;                       // 256 threads
    float2 v = ((float2*)p)[t];
    __shared__ float red[256];
    red[t] = fmaxf(v.x, v.y);
    __syncthreads();
    for (int o = 128; o > 0; o >>= 1) {
        if (t < o) red[t] = fmaxf(red[t], red[t + o]);
        __syncthreads();
    }
    float mx = red[0];
    __syncthreads();
    v.x = __expf(v.x - mx); v.y = __expf(v.y - mx);
    red[t] = v.x + v.y;
    __syncthreads();
    for (int o = 128; o > 0; o >>= 1) {
        if (t < o) red[t] += red[t + o];
        __syncthreads();
    }
    float inv = 1.0f / red[0];
    v.x *= inv; v.y *= inv;
    ((float2*)p)[t] = v;
}

// ============================================================
// 5) att[b,q,h,:] = softmax_scores[bh] @ V[b,:,h,:]
// ============================================================
__global__ __launch_bounds__(256) void av_kernel()
{
    int bh = blockIdx.y; int b = bh >> 3, h = bh & 7;
    int q0 = blockIdx.x * 64;
    const float* Wsc = g_sc + (size_t)bh * Sn * Sn;
    const float* Vp  = g_v + ((size_t)(b * Sn)) * Dn + h * HDn;

    __shared__ float Ws[32][68];   // [k][q]
    __shared__ float Vs[32][64];   // [k][e]
    int t = threadIdx.x, tx = t & 15, ty = t >> 4;

    int wq  = t >> 2;              // 0..63
    int wk4 = (t & 3) * 4;
    int vk  = t >> 4;              // 0..15
    int ve4 = (t & 15) * 4;

    float acc[4][4] = {};
    for (int k0 = 0; k0 < Sn; k0 += 32) {
        #pragma unroll
        for (int half = 0; half < 2; half++) {
            float4 w4 = *(const float4*)&Wsc[(size_t)(q0 + wq) * Sn + k0 + wk4 + half * 16];
            Ws[wk4 + half * 16 + 0][wq] = w4.x;
            Ws[wk4 + half * 16 + 1][wq] = w4.y;
            Ws[wk4 + half * 16 + 2][wq] = w4.z;
            Ws[wk4 + half * 16 + 3][wq] = w4.w;
            *(float4*)&Vs[vk + half * 16][ve4] =
                *(const float4*)&Vp[(size_t)(k0 + vk + half * 16) * Dn + ve4];
        }
        __syncthreads();
        #pragma unroll
        for (int kk = 0; kk < 32; kk++) {
            float4 av = *(const float4*)&Ws[kk][ty * 4];
            float4 bv = *(const float4*)&Vs[kk][tx * 4];
            float a[4] = {av.x, av.y, av.z, av.w};
            float b2[4] = {bv.x, bv.y, bv.z, bv.w};
            #pragma unroll
            for (int i = 0; i < 4; i++)
                #pragma unroll
                for (int j = 0; j < 4; j++)
                    acc[i][j] += a[i] * b2[j];
        }
        __syncthreads();
    }
    #pragma unroll
    for (int i = 0; i < 4; i++) {
        float4 o = make_float4(acc[i][0], acc[i][1], acc[i][2], acc[i][3]);
        *(float4*)&g_att[(size_t)(b * Sn + q0 + ty * 4 + i) * Dn + h * HDn + tx * 4] = o;
    }
}

// ============================================================
// 6) feasibility head: feas[b,s-1] = x[b,s] . feas_W + feas_b
// ============================================================
__global__ void feas_kernel(const float* __restrict__ fW,
                            const float* __restrict__ fB,
                            float* __restrict__ out)
{
    int s = blockIdx.x + 1;        // 1..510
    int b = blockIdx.y;
    const float* xr = g_x + (size_t)(b * Sn + s) * Dn;
    int t = threadIdx.x;           // 128
    float acc = 0.f;
    #pragma unroll 4
    for (int k = t; k < Dn; k += 128) acc += xr[k] * fW[k];
    __shared__ float red[128];
    red[t] = acc; __syncthreads();
    for (int o = 64; o > 0; o >>= 1) {
        if (t < o) red[t] += red[t + o];
        __syncthreads();
    }
    if (t == 0) out[OUT_FEAS_OFF + b * 510 + (s - 1)] = red[0] + fB[0];
}

// ============================================================
// 7) pointer logits: out[b, s-1] / out[b, 510 + s-1]
// ============================================================
__global__ void logits_kernel(const float* __restrict__ pW,
                              const float* __restrict__ pB,
                              float* __restrict__ out)
{
    int s = blockIdx.x + 1;        // 1..510
    int b = blockIdx.y;
    const float* xr = g_x + (size_t)(b * Sn + s) * Dn;
    int t = threadIdx.x;           // 128
    float a0 = 0.f, a1 = 0.f;
    #pragma unroll 4
    for (int k = t; k < Dn; k += 128) {
        float xv = xr[k];
        a0 += xv * pW[k * 2 + 0];
        a1 += xv * pW[k * 2 + 1];
    }
    __shared__ float r0[128], r1[128];
    r0[t] = a0; r1[t] = a1; __syncthreads();
    for (int o = 64; o > 0; o >>= 1) {
        if (t < o) { r0[t] += r0[t + o]; r1[t] += r1[t + o]; }
        __syncthreads();
    }
    if (t == 0) {
        out[b * OUT_LOGITS_PER_B + (s - 1)]       = r0[0] + pB[0];
        out[b * OUT_LOGITS_PER_B + 510 + (s - 1)] = r1[0] + pB[1];
    }
}

// ============================================================
// host orchestration
// ============================================================
extern "C" void kernel_launch(void* const* d_in, const int* in_sizes, int n_in,
                              void* d_out, int out_size)
{
    const float* sol   = (const float*)d_in[0];
    const float* cap   = (const float*)d_in[1];
    const float* emb   = (const float*)d_in[2];
    const float* srcW  = (const float*)d_in[3];
    const float* srcB  = (const float*)d_in[4];
    const float* candW = (const float*)d_in[5];
    const float* candB = (const float*)d_in[6];
    const float* depW  = (const float*)d_in[7];
    const float* depB  = (const float*)d_in[8];
    const float* feasW = (const float*)d_in[9];
    const float* feasB = (const float*)d_in[10];
    const float* Wq    = (const float*)d_in[11];
    const float* bq    = (const float*)d_in[12];
    const float* Wk    = (const float*)d_in[13];
    const float* bk    = (const float*)d_in[14];
    const float* Wv    = (const float*)d_in[15];
    const float* bv    = (const float*)d_in[16];
    const float* Wo    = (const float*)d_in[17];
    const float* bo    = (const float*)d_in[18];
    // d_in[19] = s_scale : softmax-shift-invariant, unused
    const float* W1    = (const float*)d_in[20];
    const float* b1    = (const float*)d_in[21];
    const float* W2    = (const float*)d_in[22];
    const float* b2    = (const float*)d_in[23];
    const float* ptrW  = (const float*)d_in[24];
    const float* ptrB  = (const float*)d_in[25];
    float* out = (float*)d_out;
    (void)in_sizes; (void)n_in; (void)out_size;

    float *px, *pq, *pk, *pv, *patt, *ph;
    cudaGetSymbolAddress((void**)&px,   g_x);
    cudaGetSymbolAddress((void**)&pq,   g_q);
    cudaGetSymbolAddress((void**)&pk,   g_k);
    cudaGetSymbolAddress((void**)&pv,   g_v);
    cudaGetSymbolAddress((void**)&patt, g_att);
    cudaGetSymbolAddress((void**)&ph,   g_h);

    const dim3 gProj(Dn / 64, Mn / 64);     // (8, 64)  N=512
    const dim3 gFF1(HIDn / 64, Mn / 64);    // (32, 64) N=2048
    const dim3 gScores(8, 8, 64);
    const dim3 gAv(8, 64);

    build_x_kernel<<<Mn, 256>>>(sol, cap, emb, srcW, srcB, candW, candB, depW, depB);

    for (int i = 0; i < Ln; i++) {
        const float* wq = Wq + (size_t)i * Dn * Dn;
        const float* wk = Wk + (size_t)i * Dn * Dn;
        const float* wv = Wv + (size_t)i * Dn * Dn;
        const float* wo = Wo + (size_t)i * Dn * Dn;
        const float* w1 = W1 + (size_t)i * Dn * HIDn;
        const float* w2 = W2 + (size_t)i * HIDn * Dn;

        // ---- MHA ----
        gemm_kernel<false, false><<<gProj, 256>>>(px, wq, bq + i * Dn, nullptr, pq, Dn, Dn);
        gemm_kernel<false, false><<<gProj, 256>>>(px, wk, bk + i * Dn, nullptr, pk, Dn, Dn);
        gemm_kernel<false, false><<<gProj, 256>>>(px, wv, bv + i * Dn, nullptr, pv, Dn, Dn);
        scores_kernel<<<gScores, 256>>>();
        softmax_kernel<<<Bn * Hn * Sn, 256>>>();
        av_kernel<<<gAv, 256>>>();
        gemm_kernel<false, true><<<gProj, 256>>>(patt, wo, bo + i * Dn, px, px, Dn, Dn);

        // feasibility head reads x right after layer-0 attention residual
        if (i == 0)
            feas_kernel<<<dim3(510, Bn), 128>>>(feasW, feasB, out);

        // ---- FFN ----
        gemm_kernel<true,  false><<<gFF1, 256>>>(px, w1, b1 + i * HIDn, nullptr, ph, Dn, HIDn);
        gemm_kernel<false, true ><<<gProj, 256>>>(ph, w2, b2 + i * Dn, px, px, HIDn, Dn);
    }

    logits_kernel<<<dim3(510, Bn), 128>>>(ptrW, ptrB, out);
}

// round 4
// speedup vs baseline: 2.8984x; 2.8984x over previous
#include <cuda_runtime.h>
#include <cstdint>

// ---------------- problem constants ----------------
#define Bn   8
#define Sn   512
#define Ln   6
#define Dn   512
#define Hn   8
#define HDn  64
#define HIDn 2048
#define Cn   256
#define INDIM 257
#define Mn   (Bn * Sn)          // 4096 rows

#define OUT_LOGITS_PER_B 1020   // 2 * 510
#define OUT_FEAS_OFF     (Bn * OUT_LOGITS_PER_B)   // 8160

// ---------------- scratch (device globals; no allocation) ----------------
__device__ float g_x  [Mn * Dn];             // residual stream
__device__ float g_q  [Mn * Dn];
__device__ float g_k  [Mn * Dn];
__device__ float g_att[Mn * Dn];             // attention output (pre O-proj)
__device__ float g_vT [Mn * Dn];             // V transposed per head: [b,h,e,s]
__device__ float g_sc [(size_t)Bn * Hn * Sn * Sn];   // 64 MB scores
__device__ float g_h  [Mn * HIDn];           // FFN hidden
// transposed weights ([N,K] K-major for the mma B operand)
__device__ float g_wqT[Ln * Dn * Dn];
__device__ float g_wkT[Ln * Dn * Dn];
__device__ float g_wvT[Ln * Dn * Dn];
__device__ float g_woT[Ln * Dn * Dn];
__device__ float g_w1T[Ln * Dn * HIDn];
__device__ float g_w2T[Ln * HIDn * Dn];

// ============================================================
// portable PTX helpers (sm_80+; assemble for sm_103 baseline)
// ============================================================
__device__ __forceinline__ uint32_t su32(const void* p) {
    uint32_t a;
    asm("{ .reg .u64 t; cvta.to.shared.u64 t, %1; cvt.u32.u64 %0, t; }" : "=r"(a) : "l"(p));
    return a;
}
__device__ __forceinline__ void cp_async16(uint32_t s, const void* g) {
    asm volatile("cp.async.cg.shared.global [%0], [%1], 16;" :: "r"(s), "l"(g));
}
#define CP_COMMIT() asm volatile("cp.async.commit_group;" ::: "memory")
#define CP_WAIT(n)  asm volatile("cp.async.wait_group %0;" :: "n"(n) : "memory")

__device__ __forceinline__ uint32_t to_tf32(float f) {
    uint32_t r;
    asm("cvt.rna.tf32.f32 %0, %1;" : "=r"(r) : "f"(f));
    return r;
}
#define MMA8(dd, af, b0, b1) \
    asm volatile("mma.sync.aligned.m16n8k8.row.col.f32.tf32.tf32.f32 " \
        "{%0,%1,%2,%3}, {%4,%5,%6,%7}, {%8,%9}, {%0,%1,%2,%3};" \
        : "+f"((dd)[0]), "+f"((dd)[1]), "+f"((dd)[2]), "+f"((dd)[3]) \
        : "r"((af)[0]), "r"((af)[1]), "r"((af)[2]), "r"((af)[3]), "r"(b0), "r"(b1))

// smem element index for [row][k] tile with 32-float rows, f4-XOR swizzle
__device__ __forceinline__ int swz(int row, int k) {
    return (((row << 3) + ((k >> 2) ^ (row & 7))) << 2) + (k & 3);
}

// ============================================================
// tf32 mma.sync GEMM: C[m,n] = scale*sum_k A[m,k]*B[n,k] (+bias,+Res,ReLU)
// CTA 128 x (NT*16); BK=32; 3-stage cp.async pipeline; 128 threads.
// z-batched via (zdiv, s1, s2) offsets. TRANSV: per-head-transposed output.
// ============================================================
template<int NT, bool RELU, bool RES, bool TRANSV>
__global__ __launch_bounds__(128) void mma_gemm(
    const float* __restrict__ A, int lda, size_t As1, size_t As2,
    const float* __restrict__ B, int ldb, size_t Bs1, size_t Bs2,
    float* __restrict__ C, int ldc, size_t Cs1, size_t Cs2,
    const float* __restrict__ bias, const float* __restrict__ Res,
    float scale, int K, int zdiv)
{
    constexpr int BM = 128, BK = 32;
    constexpr int BN = NT * 16;
    constexpr int NSTAGE = 3;
    constexpr int STAGE_F = (BM + BN) * BK;      // floats per stage

    extern __shared__ float smem[];
    float* sbias = smem;                          // BN floats
    float* sdata = smem + BN;

    const int t = threadIdx.x;
    const int z = blockIdx.z;
    const int zq = z / zdiv, zr = z - zq * zdiv;
    A += zq * As1 + zr * As2;
    B += zq * Bs1 + zr * Bs2;
    C += zq * Cs1 + zr * Cs2;
    const int m0 = blockIdx.y * BM;
    const int n0 = blockIdx.x * BN;

    if (bias != nullptr && t < BN) sbias[t] = bias[n0 + t];

    auto load_stage = [&](int st, int k0) {
        float* sa = sdata + (st % NSTAGE) * STAGE_F;
        float* sb = sa + BM * BK;
        #pragma unroll
        for (int i = 0; i < 8; i++) {             // A: 1024 f4 / 128 thr
            int j = t + 128 * i;
            int m = j >> 3, f = j & 7;
            uint32_t dst = su32(&sa[(((m << 3) + (f ^ (m & 7))) << 2)]);
            cp_async16(dst, A + (size_t)(m0 + m) * lda + k0 + (f << 2));
        }
        #pragma unroll
        for (int i = 0; i < BN / 16; i++) {       // B: BN*8 f4 / 128 thr
            int j = t + 128 * i;
            int n = j >> 3, f = j & 7;
            uint32_t dst = su32(&sb[(((n << 3) + (f ^ (n & 7))) << 2)]);
            cp_async16(dst, B + (size_t)(n0 + n) * ldb + k0 + (f << 2));
        }
        CP_COMMIT();
    };

    const int nst = K / BK;
    load_stage(0, 0);
    load_stage(1, BK);

    const int lane = t & 31, w = t >> 5;
    const int wm = w >> 1, wn = w & 1;            // warp grid 2x2
    const int g = lane >> 2, t4 = lane & 3;

    float d[4][NT][4] = {};                       // 64 x (NT*8) per warp

    for (int s = 0; s < nst; s++) {
        if (s < nst - 1) { CP_WAIT(1); } else { CP_WAIT(0); }
        __syncthreads();
        if (s + 2 < nst) load_stage(s + 2, (s + 2) * BK);

        const float* sa = sdata + (s % NSTAGE) * STAGE_F;
        const float* sb = sa + BM * BK;
        #pragma unroll
        for (int k8 = 0; k8 < 4; k8++) {
            const int kb = k8 << 3;
            uint32_t af[4][4];
            #pragma unroll
            for (int mt = 0; mt < 4; mt++) {
                int r = wm * 64 + mt * 16 + g;
                af[mt][0] = to_tf32(sa[swz(r,     kb + t4)]);
                af[mt][1] = to_tf32(sa[swz(r + 8, kb + t4)]);
                af[mt][2] = to_tf32(sa[swz(r,     kb + t4 + 4)]);
                af[mt][3] = to_tf32(sa[swz(r + 8, kb + t4 + 4)]);
            }
            #pragma unroll
            for (int nt = 0; nt < NT; nt++) {
                int n = wn * NT * 8 + nt * 8 + g;
                uint32_t b0 = to_tf32(sb[swz(n, kb + t4)]);
                uint32_t b1 = to_tf32(sb[swz(n, kb + t4 + 4)]);
                #pragma unroll
                for (int mt = 0; mt < 4; mt++) MMA8(d[mt][nt], af[mt], b0, b1);
            }
        }
    }

    // ---------------- epilogue ----------------
    const int colw = wn * NT * 8;                 // warp col base within tile
    #pragma unroll
    for (int mt = 0; mt < 4; mt++) {
        #pragma unroll
        for (int h2 = 0; h2 < 2; h2++) {
            const int m = m0 + wm * 64 + mt * 16 + g + h2 * 8;
            if (TRANSV) {
                #pragma unroll
                for (int nt = 0; nt < NT; nt++) {
                    int cl = colw + nt * 8 + 2 * t4;          // local col
                    int gc = n0 + cl;                          // global col
                    float v0 = d[mt][nt][h2 * 2]     * scale;
                    float v1 = d[mt][nt][h2 * 2 + 1] * scale;
                    if (bias != nullptr) { v0 += sbias[cl]; v1 += sbias[cl + 1]; }
                    int hh = gc >> 6, e = gc & 63;
                    size_t base = ((size_t)((m >> 9) * Hn + hh) * 64 + e) * 512
                                  + (size_t)(m & 511);
                    C[base]       = v0;
                    C[base + 512] = v1;
                }
            } else {
                float* crow = C + (size_t)m * ldc + n0;
                const float* rrow = RES ? (Res + (size_t)m * ldc + n0) : nullptr;
                #pragma unroll
                for (int nt = 0; nt < NT; nt++) {
                    int cl = colw + nt * 8 + 2 * t4;
                    float v0 = d[mt][nt][h2 * 2]     * scale;
                    float v1 = d[mt][nt][h2 * 2 + 1] * scale;
                    if (bias != nullptr) { v0 += sbias[cl]; v1 += sbias[cl + 1]; }
                    if (RELU) { v0 = fmaxf(v0, 0.f); v1 = fmaxf(v1, 0.f); }
                    if (RES) {
                        float2 r = *(const float2*)(rrow + cl);
                        v0 += r.x; v1 += r.y;
                    }
                    *(float2*)(crow + cl) = make_float2(v0, v1);
                }
            }
        }
    }
}

// ============================================================
// weight transpose: dst[z][c][r] = src[z][r][c]   (R x C per z)
// ============================================================
__global__ void transpose_kernel(const float* __restrict__ src, float* __restrict__ dst,
                                 int R, int C)
{
    __shared__ float tile[32][33];
    size_t zoff = (size_t)blockIdx.z * R * C;
    int c0 = blockIdx.x * 32, r0 = blockIdx.y * 32;
    int tx = threadIdx.x, ty = threadIdx.y;       // 32 x 8
    #pragma unroll
    for (int j = 0; j < 32; j += 8)
        tile[ty + j][tx] = src[zoff + (size_t)(r0 + ty + j) * C + c0 + tx];
    __syncthreads();
    #pragma unroll
    for (int j = 0; j < 32; j += 8)
        dst[zoff + (size_t)(c0 + ty + j) * R + r0 + tx] = tile[tx][ty + j];
}

// ============================================================
// build x = class_proj(concat(embed[idx], nd))  per row
// ============================================================
__global__ void build_x_kernel(const float* __restrict__ sol,
                               const float* __restrict__ cap,
                               const float* __restrict__ emb,
                               const float* __restrict__ srcW, const float* __restrict__ srcB,
                               const float* __restrict__ candW, const float* __restrict__ candB,
                               const float* __restrict__ depW, const float* __restrict__ depB)
{
    int row = blockIdx.x;
    int b = row / Sn, s = row % Sn;
    __shared__ float xin[INDIM];
    int t = threadIdx.x;

    int idx = (int)sol[(size_t)row * 4 + 0];
    xin[t] = emb[(size_t)idx * Cn + t];
    if (t == 0) {
        float rem = sol[(size_t)(b * Sn) * 4 + 3];
        float nd = (s == 0) ? 0.0f : 2.0f * (sol[(size_t)row * 4 + 2] - rem) / cap[b];
        xin[Cn] = nd;
    }
    __syncthreads();

    const float* W; const float* bb;
    if (s == 0)           { W = srcW;  bb = srcB;  }
    else if (s == Sn - 1) { W = depW;  bb = depB;  }
    else                  { W = candW; bb = candB; }

    int c = t;
    float acc0 = bb[c], acc1 = bb[c + 256];
    #pragma unroll 4
    for (int k = 0; k < INDIM; k++) {
        float xv = xin[k];
        acc0 += xv * W[k * Dn + c];
        acc1 += xv * W[k * Dn + c + 256];
    }
    g_x[(size_t)row * Dn + c]       = acc0;
    g_x[(size_t)row * Dn + c + 256] = acc1;
}

// ============================================================
// row softmax over the 512-wide score rows
// ============================================================
__global__ void softmax_kernel()
{
    size_t row = blockIdx.x;
    float* p = g_sc + row * Sn;
    int t = threadIdx.x;                       // 256 threads
    float2 v = ((float2*)p)[t];
    __shared__ float red[256];
    red[t] = fmaxf(v.x, v.y);
    __syncthreads();
    for (int o = 128; o > 0; o >>= 1) {
        if (t < o) red[t] = fmaxf(red[t], red[t + o]);
        __syncthreads();
    }
    float mx = red[0];
    __syncthreads();
    v.x = __expf(v.x - mx); v.y = __expf(v.y - mx);
    red[t] = v.x + v.y;
    __syncthreads();
    for (int o = 128; o > 0; o >>= 1) {
        if (t < o) red[t] += red[t + o];
        __syncthreads();
    }
    float inv = 1.0f / red[0];
    v.x *= inv; v.y *= inv;
    ((float2*)p)[t] = v;
}

// ============================================================
// feasibility head
// ============================================================
__global__ void feas_kernel(const float* __restrict__ fW,
                            const float* __restrict__ fB,
                            float* __restrict__ out)
{
    int s = blockIdx.x + 1;
    int b = blockIdx.y;
    const float* xr = g_x + (size_t)(b * Sn + s) * Dn;
    int t = threadIdx.x;
    float acc = 0.f;
    #pragma unroll 4
    for (int k = t; k < Dn; k += 128) acc += xr[k] * fW[k];
    __shared__ float red[128];
    red[t] = acc; __syncthreads();
    for (int o = 64; o > 0; o >>= 1) {
        if (t < o) red[t] += red[t + o];
        __syncthreads();
    }
    if (t == 0) out[OUT_FEAS_OFF + b * 510 + (s - 1)] = red[0] + fB[0];
}

// ============================================================
// pointer logits
// ============================================================
__global__ void logits_kernel(const float* __restrict__ pW,
                              const float* __restrict__ pB,
                              float* __restrict__ out)
{
    int s = blockIdx.x + 1;
    int b = blockIdx.y;
    const float* xr = g_x + (size_t)(b * Sn + s) * Dn;
    int t = threadIdx.x;
    float a0 = 0.f, a1 = 0.f;
    #pragma unroll 4
    for (int k = t; k < Dn; k += 128) {
        float xv = xr[k];
        a0 += xv * pW[k * 2 + 0];
        a1 += xv * pW[k * 2 + 1];
    }
    __shared__ float r0[128], r1[128];
    r0[t] = a0; r1[t] = a1; __syncthreads();
    for (int o = 64; o > 0; o >>= 1) {
        if (t < o) { r0[t] += r0[t + o]; r1[t] += r1[t + o]; }
        __syncthreads();
    }
    if (t == 0) {
        out[b * OUT_LOGITS_PER_B + (s - 1)]       = r0[0] + pB[0];
        out[b * OUT_LOGITS_PER_B + 510 + (s - 1)] = r1[0] + pB[1];
    }
}

// ============================================================
// host orchestration
// ============================================================
extern "C" void kernel_launch(void* const* d_in, const int* in_sizes, int n_in,
                              void* d_out, int out_size)
{
    const float* sol   = (const float*)d_in[0];
    const float* cap   = (const float*)d_in[1];
    const float* emb   = (const float*)d_in[2];
    const float* srcW  = (const float*)d_in[3];
    const float* srcB  = (const float*)d_in[4];
    const float* candW = (const float*)d_in[5];
    const float* candB = (const float*)d_in[6];
    const float* depW  = (const float*)d_in[7];
    const float* depB  = (const float*)d_in[8];
    const float* feasW = (const float*)d_in[9];
    const float* feasB = (const float*)d_in[10];
    const float* Wq    = (const float*)d_in[11];
    const float* bq    = (const float*)d_in[12];
    const float* Wk    = (const float*)d_in[13];
    const float* bk    = (const float*)d_in[14];
    const float* Wv    = (const float*)d_in[15];
    const float* bv    = (const float*)d_in[16];
    const float* Wo    = (const float*)d_in[17];
    const float* bo    = (const float*)d_in[18];
    // d_in[19] = s_scale : softmax-shift-invariant, unused
    const float* W1    = (const float*)d_in[20];
    const float* b1    = (const float*)d_in[21];
    const float* W2    = (const float*)d_in[22];
    const float* b2    = (const float*)d_in[23];
    const float* ptrW  = (const float*)d_in[24];
    const float* ptrB  = (const float*)d_in[25];
    float* out = (float*)d_out;
    (void)in_sizes; (void)n_in; (void)out_size;

    float *px, *pq, *pk, *patt, *pvT, *psc, *ph;
    float *pwqT, *pwkT, *pwvT, *pwoT, *pw1T, *pw2T;
    cudaGetSymbolAddress((void**)&px,   g_x);
    cudaGetSymbolAddress((void**)&pq,   g_q);
    cudaGetSymbolAddress((void**)&pk,   g_k);
    cudaGetSymbolAddress((void**)&patt, g_att);
    cudaGetSymbolAddress((void**)&pvT,  g_vT);
    cudaGetSymbolAddress((void**)&psc,  g_sc);
    cudaGetSymbolAddress((void**)&ph,   g_h);
    cudaGetSymbolAddress((void**)&pwqT, g_wqT);
    cudaGetSymbolAddress((void**)&pwkT, g_wkT);
    cudaGetSymbolAddress((void**)&pwvT, g_wvT);
    cudaGetSymbolAddress((void**)&pwoT, g_woT);
    cudaGetSymbolAddress((void**)&pw1T, g_w1T);
    cudaGetSymbolAddress((void**)&pw2T, g_w2T);

    const int SM8 = (128 + 3 * (128 + 128) * 32) * 4;   // 98816 B
    const int SM4 = ( 64 + 3 * (128 +  64) * 32) * 4;   // 73984 B
    cudaFuncSetAttribute(mma_gemm<8, false, false, false>, cudaFuncAttributeMaxDynamicSharedMemorySize, SM8);
    cudaFuncSetAttribute(mma_gemm<8, false, false, true >, cudaFuncAttributeMaxDynamicSharedMemorySize, SM8);
    cudaFuncSetAttribute(mma_gemm<8, false, true,  false>, cudaFuncAttributeMaxDynamicSharedMemorySize, SM8);
    cudaFuncSetAttribute(mma_gemm<8, true,  false, false>, cudaFuncAttributeMaxDynamicSharedMemorySize, SM8);
    cudaFuncSetAttribute(mma_gemm<4, false, false, false>, cudaFuncAttributeMaxDynamicSharedMemorySize, SM4);

    const size_t DD = (size_t)Dn * Dn;
    const size_t DH = (size_t)Dn * HIDn;
    const size_t SS = (size_t)Sn * Sn;
    const size_t SD = (size_t)Sn * Dn;

    // ---- transpose all weights to [N,K] K-major ----
    dim3 tb(32, 8);
    transpose_kernel<<<dim3(16, 16, Ln), tb>>>(Wq, pwqT, Dn, Dn);
    transpose_kernel<<<dim3(16, 16, Ln), tb>>>(Wk, pwkT, Dn, Dn);
    transpose_kernel<<<dim3(16, 16, Ln), tb>>>(Wv, pwvT, Dn, Dn);
    transpose_kernel<<<dim3(16, 16, Ln), tb>>>(Wo, pwoT, Dn, Dn);
    transpose_kernel<<<dim3(64, 16, Ln), tb>>>(W1, pw1T, Dn, HIDn);   // -> [2048,512]
    transpose_kernel<<<dim3(16, 64, Ln), tb>>>(W2, pw2T, HIDn, Dn);   // -> [512,2048]

    build_x_kernel<<<Mn, 256>>>(sol, cap, emb, srcW, srcB, candW, candB, depW, depB);

    const dim3 gProj(Dn / 128, Mn / 128, 1);      // (4, 32)
    const dim3 gFF1(HIDn / 128, Mn / 128, 1);     // (16, 32)
    const dim3 gSc(Sn / 128, Sn / 128, Bn * Hn);  // (4, 4, 64)
    const dim3 gAv(1, Sn / 128, Bn * Hn);         // (1, 4, 64), BN=64

    for (int i = 0; i < Ln; i++) {
        // ---- MHA projections (V stored per-head-transposed) ----
        mma_gemm<8, false, false, false><<<gProj, 128, SM8>>>(
            px, Dn, 0, 0,  pwqT + i * DD, Dn, 0, 0,  pq, Dn, 0, 0,
            bq + i * Dn, nullptr, 1.0f, Dn, 1);
        mma_gemm<8, false, false, false><<<gProj, 128, SM8>>>(
            px, Dn, 0, 0,  pwkT + i * DD, Dn, 0, 0,  pk, Dn, 0, 0,
            bk + i * Dn, nullptr, 1.0f, Dn, 1);
        mma_gemm<8, false, false, true><<<gProj, 128, SM8>>>(
            px, Dn, 0, 0,  pwvT + i * DD, Dn, 0, 0,  pvT, Dn, 0, 0,
            bv + i * Dn, nullptr, 1.0f, Dn, 1);

        // ---- scores = 0.125 * Q K^T per (b,h); +s*log(n) softmax-invariant ----
        mma_gemm<8, false, false, false><<<gSc, 128, SM8>>>(
            pq, Dn, SD, HDn,  pk, Dn, SD, HDn,  psc, Sn, Hn * SS, SS,
            nullptr, nullptr, 0.125f, HDn, Hn);

        softmax_kernel<<<Bn * Hn * Sn, 256>>>();

        // ---- att = probs @ V per (b,h) ----
        mma_gemm<4, false, false, false><<<gAv, 128, SM4>>>(
            psc, Sn, Hn * SS, SS,  pvT, Sn, SD, (size_t)HDn * Sn,
            patt, Dn, SD, HDn,  nullptr, nullptr, 1.0f, Sn, Hn);

        // ---- O projection + residual ----
        mma_gemm<8, false, true, false><<<gProj, 128, SM8>>>(
            patt, Dn, 0, 0,  pwoT + i * DD, Dn, 0, 0,  px, Dn, 0, 0,
            bo + i * Dn, px, 1.0f, Dn, 1);

        // feasibility head reads x right after layer-0 attention residual
        if (i == 0)
            feas_kernel<<<dim3(510, Bn), 128>>>(feasW, feasB, out);

        // ---- FFN ----
        mma_gemm<8, true, false, false><<<gFF1, 128, SM8>>>(
            px, Dn, 0, 0,  pw1T + i * DH, Dn, 0, 0,  ph, HIDn, 0, 0,
            b1 + i * HIDn, nullptr, 1.0f, Dn, 1);
        mma_gemm<8, false, true, false><<<gProj, 128, SM8>>>(
            ph, HIDn, 0, 0,  pw2T + i * DH, HIDn, 0, 0,  px, Dn, 0, 0,
            b2 + i * Dn, px, 1.0f, HIDn, 1);
    }

    logits_kernel<<<dim3(510, Bn), 128>>>(ptrW, ptrB, out);
}

// round 5
// speedup vs baseline: 3.6594x; 1.2626x over previous
#include <cuda_runtime.h>
#include <cstdint>

// ---------------- problem constants ----------------
#define Bn   8
#define Sn   512
#define Ln   6
#define Dn   512
#define Hn   8
#define HDn  64
#define HIDn 2048
#define Cn   256
#define INDIM 257
#define Mn   (Bn * Sn)          // 4096 rows

#define OUT_LOGITS_PER_B 1020   // 2 * 510
#define OUT_FEAS_OFF     (Bn * OUT_LOGITS_PER_B)   // 8160

// ---------------- scratch (device globals; no allocation) ----------------
__device__ float g_x  [Mn * Dn];             // residual stream
__device__ float g_q  [Mn * Dn];             // Q (tf32 bits)
__device__ float g_k  [Mn * Dn];             // K (tf32 bits)
__device__ float g_att[Mn * Dn];             // attention output (pre O-proj)
__device__ float g_vT [Mn * Dn];             // V^T per head [b,h,e,s] (tf32 bits)
__device__ float g_h  [Mn * HIDn];           // FFN hidden
// transposed weights ([N,K] K-major for the mma B operand)
__device__ float g_wqkvT[Ln * 1536 * Dn];    // concat QKV [1536,512] per layer
__device__ float g_bqkv [Ln * 1536];
__device__ float g_woT[Ln * Dn * Dn];
__device__ float g_w1T[Ln * Dn * HIDn];
__device__ float g_w2T[Ln * HIDn * Dn];

// ============================================================
// portable PTX helpers (sm_80+; assemble for sm_103 baseline)
// ============================================================
__device__ __forceinline__ uint32_t su32(const void* p) {
    uint32_t a;
    asm("{ .reg .u64 t; cvta.to.shared.u64 t, %1; cvt.u32.u64 %0, t; }" : "=r"(a) : "l"(p));
    return a;
}
__device__ __forceinline__ void cp_async16(uint32_t s, const void* g) {
    asm volatile("cp.async.cg.shared.global [%0], [%1], 16;" :: "r"(s), "l"(g));
}
#define CP_COMMIT() asm volatile("cp.async.commit_group;" ::: "memory")
#define CP_WAIT(n)  asm volatile("cp.async.wait_group %0;" :: "n"(n) : "memory")

__device__ __forceinline__ uint32_t to_tf32(float f) {
    uint32_t r;
    asm("cvt.rna.tf32.f32 %0, %1;" : "=r"(r) : "f"(f));
    return r;
}
#define MMA8(dd, af, b0, b1) \
    asm volatile("mma.sync.aligned.m16n8k8.row.col.f32.tf32.tf32.f32 " \
        "{%0,%1,%2,%3}, {%4,%5,%6,%7}, {%8,%9}, {%0,%1,%2,%3};" \
        : "+f"((dd)[0]), "+f"((dd)[1]), "+f"((dd)[2]), "+f"((dd)[3]) \
        : "r"((af)[0]), "r"((af)[1]), "r"((af)[2]), "r"((af)[3]), "r"(b0), "r"(b1))

// smem element index for [row][k] tile with 32-float rows, f4-XOR swizzle
__device__ __forceinline__ int swz(int row, int k) {
    return (((row << 3) + ((k >> 2) ^ (row & 7))) << 2) + (k & 3);
}

// ============================================================
// tf32 mma.sync GEMM: C = scale*(A B^T) (+bias, +Res, ReLU)
// CTA 128 x (NT*16); BK=32; 3-stage cp.async; 128 threads.
// QKV: fused epilogue routes to q (C) / k (Ck) / vT (Cv), stores tf32 bits.
// ============================================================
template<int NT, bool RELU, bool RES, bool QKV>
__global__ __launch_bounds__(128) void mma_gemm(
    const float* __restrict__ A, int lda, size_t As1, size_t As2,
    const float* __restrict__ B, int ldb, size_t Bs1, size_t Bs2,
    float* __restrict__ C, int ldc, size_t Cs1, size_t Cs2,
    const float* __restrict__ bias, const float* __restrict__ Res,
    float scale, int K, int zdiv,
    float* __restrict__ Ck, float* __restrict__ Cv)
{
    constexpr int BM = 128, BK = 32;
    constexpr int BN = NT * 16;
    constexpr int NSTAGE = 3;
    constexpr int STAGE_F = (BM + BN) * BK;

    extern __shared__ float smem[];
    float* sbias = smem;
    float* sdata = smem + BN;

    const int t = threadIdx.x;
    const int z = blockIdx.z;
    const int zq = z / zdiv, zr = z - zq * zdiv;
    A += zq * As1 + zr * As2;
    B += zq * Bs1 + zr * Bs2;
    C += zq * Cs1 + zr * Cs2;
    const int m0 = blockIdx.y * BM;
    const int n0 = blockIdx.x * BN;

    if (bias != nullptr && t < BN) sbias[t] = bias[n0 + t];

    auto load_stage = [&](int st, int k0) {
        float* sa = sdata + (st % NSTAGE) * STAGE_F;
        float* sb = sa + BM * BK;
        #pragma unroll
        for (int i = 0; i < 8; i++) {
            int j = t + 128 * i;
            int m = j >> 3, f = j & 7;
            uint32_t dst = su32(&sa[(((m << 3) + (f ^ (m & 7))) << 2)]);
            cp_async16(dst, A + (size_t)(m0 + m) * lda + k0 + (f << 2));
        }
        #pragma unroll
        for (int i = 0; i < BN / 16; i++) {
            int j = t + 128 * i;
            int n = j >> 3, f = j & 7;
            uint32_t dst = su32(&sb[(((n << 3) + (f ^ (n & 7))) << 2)]);
            cp_async16(dst, B + (size_t)(n0 + n) * ldb + k0 + (f << 2));
        }
        CP_COMMIT();
    };

    const int nst = K / BK;
    load_stage(0, 0);
    load_stage(1, BK);

    const int lane = t & 31, w = t >> 5;
    const int wm = w >> 1, wn = w & 1;
    const int g = lane >> 2, t4 = lane & 3;

    float d[4][NT][4] = {};

    for (int s = 0; s < nst; s++) {
        if (s < nst - 1) { CP_WAIT(1); } else { CP_WAIT(0); }
        __syncthreads();
        if (s + 2 < nst) load_stage(s + 2, (s + 2) * BK);

        const float* sa = sdata + (s % NSTAGE) * STAGE_F;
        const float* sb = sa + BM * BK;
        #pragma unroll
        for (int k8 = 0; k8 < 4; k8++) {
            const int kb = k8 << 3;
            uint32_t af[4][4];
            #pragma unroll
            for (int mt = 0; mt < 4; mt++) {
                int r = wm * 64 + mt * 16 + g;
                af[mt][0] = to_tf32(sa[swz(r,     kb + t4)]);
                af[mt][1] = to_tf32(sa[swz(r + 8, kb + t4)]);
                af[mt][2] = to_tf32(sa[swz(r,     kb + t4 + 4)]);
                af[mt][3] = to_tf32(sa[swz(r + 8, kb + t4 + 4)]);
            }
            #pragma unroll
            for (int nt = 0; nt < NT; nt++) {
                int n = wn * NT * 8 + nt * 8 + g;
                uint32_t b0 = to_tf32(sb[swz(n, kb + t4)]);
                uint32_t b1 = to_tf32(sb[swz(n, kb + t4 + 4)]);
                #pragma unroll
                for (int mt = 0; mt < 4; mt++) MMA8(d[mt][nt], af[mt], b0, b1);
            }
        }
    }

    // ---------------- epilogue ----------------
    const int colw = wn * NT * 8;
    #pragma unroll
    for (int mt = 0; mt < 4; mt++) {
        #pragma unroll
        for (int h2 = 0; h2 < 2; h2++) {
            const int m = m0 + wm * 64 + mt * 16 + g + h2 * 8;
            if (QKV) {
                const int region = n0 >> 9;       // 0=Q, 1=K, 2=V
                const int nb = n0 & 511;
                if (region < 2) {
                    float* crow = (region == 0 ? C : Ck) + (size_t)m * 512 + nb;
                    #pragma unroll
                    for (int nt = 0; nt < NT; nt++) {
                        int cl = colw + nt * 8 + 2 * t4;
                        float v0 = d[mt][nt][h2 * 2]     + sbias[cl];
                        float v1 = d[mt][nt][h2 * 2 + 1] + sbias[cl + 1];
                        *(float2*)(crow + cl) = make_float2(
                            __uint_as_float(to_tf32(v0)), __uint_as_float(to_tf32(v1)));
                    }
                } else {
                    #pragma unroll
                    for (int nt = 0; nt < NT; nt++) {
                        int cl = colw + nt * 8 + 2 * t4;
                        float v0 = d[mt][nt][h2 * 2]     + sbias[cl];
                        float v1 = d[mt][nt][h2 * 2 + 1] + sbias[cl + 1];
                        int gc = nb + cl;
                        int hh = gc >> 6, e = gc & 63;
                        size_t base = ((size_t)((m >> 9) * Hn + hh) * 64 + e) * 512
                                      + (size_t)(m & 511);
                        Cv[base]       = __uint_as_float(to_tf32(v0));
                        Cv[base + 512] = __uint_as_float(to_tf32(v1));
                    }
                }
            } else {
                float* crow = C + (size_t)m * ldc + n0;
                const float* rrow = RES ? (Res + (size_t)m * ldc + n0) : nullptr;
                #pragma unroll
                for (int nt = 0; nt < NT; nt++) {
                    int cl = colw + nt * 8 + 2 * t4;
                    float v0 = d[mt][nt][h2 * 2]     * scale;
                    float v1 = d[mt][nt][h2 * 2 + 1] * scale;
                    if (bias != nullptr) { v0 += sbias[cl]; v1 += sbias[cl + 1]; }
                    if (RELU) { v0 = fmaxf(v0, 0.f); v1 = fmaxf(v1, 0.f); }
                    if (RES) {
                        float2 r = *(const float2*)(rrow + cl);
                        v0 += r.x; v1 += r.y;
                    }
                    *(float2*)(crow + cl) = make_float2(v0, v1);
                }
            }
        }
    }
}

// ============================================================
// flash attention: per (b,h,qtile 128): online softmax, S never hits gmem
// 256 threads (8 warps), warp w owns q-rows [w*16, w*16+16)
// smem: P/Q 64KB | 2 x (K 32KB + V 32KB)  = 192KB
// ============================================================
#define FLASH_SMEM 196608
#define NEG_INF (-1e30f)

__global__ __launch_bounds__(256) void flash_kernel()
{
    extern __shared__ float smem[];
    float* Ps = smem;                          // 16384 floats (P; Q staging)

    const int t = threadIdx.x;
    const int lane = t & 31, w = t >> 5;
    const int g = lane >> 2, t4 = lane & 3;
    const int q0 = blockIdx.x * 128;
    const int b = blockIdx.y >> 3, h = blockIdx.y & 7;
    const int r0 = w * 16;

    const float* qg = g_q  + (size_t)(b * Sn + q0) * Dn + h * HDn;
    const float* kg = g_k  + (size_t)(b * Sn) * Dn + h * HDn;
    const float* vg = g_vT + (size_t)(b * Hn + h) * HDn * Sn;

    // ---- stage Q into Ps (2 chunks of [128][32]) ----
    #pragma unroll
    for (int i = 0; i < 8; i++) {
        int j = t + 256 * i;
        int r = j >> 4, f = j & 15;
        int ch = f >> 3, fc = f & 7;
        uint32_t dst = su32(&Ps[ch * 4096 + (((r << 3) + (fc ^ (r & 7))) << 2)]);
        cp_async16(dst, qg + (size_t)r * Dn + f * 4);
    }
    CP_COMMIT();

    auto load_kv = [&](int tile, int st) {
        float* kb = smem + 16384 + st * 16384;
        float* vb = kb + 8192;
        #pragma unroll
        for (int i = 0; i < 8; i++) {          // K tile [128 s][64 e] -> 2 chunks
            int j = t + 256 * i;
            int r = j >> 4, f = j & 15;
            int ch = f >> 3, fc = f & 7;
            uint32_t dst = su32(&kb[ch * 4096 + (((r << 3) + (fc ^ (r & 7))) << 2)]);
            cp_async16(dst, kg + (size_t)(tile * 128 + r) * Dn + f * 4);
        }
        #pragma unroll
        for (int i = 0; i < 8; i++) {          // V^T tile [64 e][128 s] -> 4 chunks
            int j = t + 256 * i;
            int e = j >> 5, f = j & 31;
            int ch = f >> 3, fc = f & 7;
            uint32_t dst = su32(&vb[ch * 2048 + (((e << 3) + (fc ^ (e & 7))) << 2)]);
            cp_async16(dst, vg + (size_t)e * Sn + tile * 128 + f * 4);
        }
        CP_COMMIT();
    };
    load_kv(0, 0);
    load_kv(1, 1);

    // ---- Q fragments to regs (held for whole kernel) ----
    CP_WAIT(2);
    __syncthreads();
    uint32_t qf[8][4];
    #pragma unroll
    for (int c = 0; c < 2; c++)
        #pragma unroll
        for (int k8 = 0; k8 < 4; k8++) {
            const float* base = Ps + c * 4096;
            qf[c * 4 + k8][0] = __float_as_uint(base[swz(r0 + g,     k8 * 8 + t4)]);
            qf[c * 4 + k8][1] = __float_as_uint(base[swz(r0 + g + 8, k8 * 8 + t4)]);
            qf[c * 4 + k8][2] = __float_as_uint(base[swz(r0 + g,     k8 * 8 + t4 + 4)]);
            qf[c * 4 + k8][3] = __float_as_uint(base[swz(r0 + g + 8, k8 * 8 + t4 + 4)]);
        }
    __syncthreads();

    float m0 = NEG_INF, m1 = NEG_INF, l0 = 0.f, l1 = 0.f;
    float o[8][4] = {};

    for (int tile = 0; tile < 4; tile++) {
        if (tile < 3) { CP_WAIT(1); } else { CP_WAIT(0); }
        __syncthreads();
        const float* kb = smem + 16384 + (tile & 1) * 16384;
        const float* vb = kb + 8192;

        // ---- S = Q K^T ----
        float s[16][4];
        #pragma unroll
        for (int nt = 0; nt < 16; nt++)
            #pragma unroll
            for (int j = 0; j < 4; j++) s[nt][j] = 0.f;
        #pragma unroll
        for (int c = 0; c < 2; c++)
            #pragma unroll
            for (int k8 = 0; k8 < 4; k8++) {
                const int kk = k8 * 8;
                #pragma unroll
                for (int nt = 0; nt < 16; nt++) {
                    uint32_t b0 = __float_as_uint(kb[c * 4096 + swz(nt * 8 + g, kk + t4)]);
                    uint32_t b1 = __float_as_uint(kb[c * 4096 + swz(nt * 8 + g, kk + t4 + 4)]);
                    MMA8(s[nt], qf[c * 4 + k8], b0, b1);
                }
            }

        // ---- online softmax update ----
        float rm0 = NEG_INF, rm1 = NEG_INF;
        #pragma unroll
        for (int nt = 0; nt < 16; nt++) {
            s[nt][0] *= 0.125f; s[nt][1] *= 0.125f;
            s[nt][2] *= 0.125f; s[nt][3] *= 0.125f;
            rm0 = fmaxf(rm0, fmaxf(s[nt][0], s[nt][1]));
            rm1 = fmaxf(rm1, fmaxf(s[nt][2], s[nt][3]));
        }
        rm0 = fmaxf(rm0, __shfl_xor_sync(0xFFFFFFFF, rm0, 1));
        rm0 = fmaxf(rm0, __shfl_xor_sync(0xFFFFFFFF, rm0, 2));
        rm1 = fmaxf(rm1, __shfl_xor_sync(0xFFFFFFFF, rm1, 1));
        rm1 = fmaxf(rm1, __shfl_xor_sync(0xFFFFFFFF, rm1, 2));
        float mn0 = fmaxf(m0, rm0), mn1 = fmaxf(m1, rm1);
        float a0 = __expf(m0 - mn0), a1 = __expf(m1 - mn1);
        m0 = mn0; m1 = mn1;

        float rs0 = 0.f, rs1 = 0.f;
        #pragma unroll
        for (int nt = 0; nt < 16; nt++) {
            float p0 = __expf(s[nt][0] - m0);
            float p1 = __expf(s[nt][1] - m0);
            float p2 = __expf(s[nt][2] - m1);
            float p3 = __expf(s[nt][3] - m1);
            rs0 += p0 + p1; rs1 += p2 + p3;
            int col = nt * 8 + 2 * t4;
            int ch = col >> 5, kc = col & 31;
            *(float2*)&Ps[ch * 4096 + swz(r0 + g, kc)] = make_float2(
                __uint_as_float(to_tf32(p0)), __uint_as_float(to_tf32(p1)));
            *(float2*)&Ps[ch * 4096 + swz(r0 + g + 8, kc)] = make_float2(
                __uint_as_float(to_tf32(p2)), __uint_as_float(to_tf32(p3)));
        }
        rs0 += __shfl_xor_sync(0xFFFFFFFF, rs0, 1);
        rs0 += __shfl_xor_sync(0xFFFFFFFF, rs0, 2);
        rs1 += __shfl_xor_sync(0xFFFFFFFF, rs1, 1);
        rs1 += __shfl_xor_sync(0xFFFFFFFF, rs1, 2);
        l0 = l0 * a0 + rs0;
        l1 = l1 * a1 + rs1;
        #pragma unroll
        for (int nt = 0; nt < 8; nt++) {
            o[nt][0] *= a0; o[nt][1] *= a0;
            o[nt][2] *= a1; o[nt][3] *= a1;
        }
        __syncwarp();

        // ---- O += P @ V^T ----
        #pragma unroll
        for (int k8g = 0; k8g < 16; k8g++) {
            const int ch = k8g >> 2, kk = (k8g & 3) * 8;
            uint32_t af[4];
            af[0] = __float_as_uint(Ps[ch * 4096 + swz(r0 + g,     kk + t4)]);
            af[1] = __float_as_uint(Ps[ch * 4096 + swz(r0 + g + 8, kk + t4)]);
            af[2] = __float_as_uint(Ps[ch * 4096 + swz(r0 + g,     kk + t4 + 4)]);
            af[3] = __float_as_uint(Ps[ch * 4096 + swz(r0 + g + 8, kk + t4 + 4)]);
            #pragma unroll
            for (int nt = 0; nt < 8; nt++) {
                uint32_t b0 = __float_as_uint(vb[ch * 2048 + swz(nt * 8 + g, kk + t4)]);
                uint32_t b1 = __float_as_uint(vb[ch * 2048 + swz(nt * 8 + g, kk + t4 + 4)]);
                MMA8(o[nt], af, b0, b1);
            }
        }
        __syncthreads();
        if (tile + 2 < 4) load_kv(tile + 2, tile & 1);
    }

    // ---- epilogue: O / l -> g_att ----
    float inv0 = 1.0f / l0, inv1 = 1.0f / l1;
    float* orow0 = g_att + (size_t)(b * Sn + q0 + r0 + g) * Dn + h * HDn;
    float* orow1 = orow0 + 8 * Dn;
    #pragma unroll
    for (int nt = 0; nt < 8; nt++) {
        int col = nt * 8 + 2 * t4;
        *(float2*)(orow0 + col) = make_float2(o[nt][0] * inv0, o[nt][1] * inv0);
        *(float2*)(orow1 + col) = make_float2(o[nt][2] * inv1, o[nt][3] * inv1);
    }
}

// ============================================================
// weight transpose: dst[zdst + c*R + r] = src[z][r][c]
// ============================================================
__global__ void transpose_kernel(const float* __restrict__ src, float* __restrict__ dst,
                                 int R, int C, size_t zstride, size_t doff)
{
    __shared__ float tile[32][33];
    size_t zsrc = (size_t)blockIdx.z * R * C;
    size_t zdst = (size_t)blockIdx.z * zstride + doff;
    int c0 = blockIdx.x * 32, r0 = blockIdx.y * 32;
    int tx = threadIdx.x, ty = threadIdx.y;       // 32 x 8
    #pragma unroll
    for (int j = 0; j < 32; j += 8)
        tile[ty + j][tx] = src[zsrc + (size_t)(r0 + ty + j) * C + c0 + tx];
    __syncthreads();
    #pragma unroll
    for (int j = 0; j < 32; j += 8)
        dst[zdst + (size_t)(c0 + ty + j) * R + r0 + tx] = tile[tx][ty + j];
}

__global__ void packbias_kernel(const float* __restrict__ bq, const float* __restrict__ bk,
                                const float* __restrict__ bv, float* __restrict__ dst)
{
    int i = blockIdx.x, t = threadIdx.x;   // Ln x 512
    dst[i * 1536 + t]        = bq[i * 512 + t];
    dst[i * 1536 + 512 + t]  = bk[i * 512 + t];
    dst[i * 1536 + 1024 + t] = bv[i * 512 + t];
}

// ============================================================
// build x = class_proj(concat(embed[idx], nd))  per row
// ============================================================
__global__ void build_x_kernel(const float* __restrict__ sol,
                               const float* __restrict__ cap,
                               const float* __restrict__ emb,
                               const float* __restrict__ srcW, const float* __restrict__ srcB,
                               const float* __restrict__ candW, const float* __restrict__ candB,
                               const float* __restrict__ depW, const float* __restrict__ depB)
{
    int row = blockIdx.x;
    int b = row / Sn, s = row % Sn;
    __shared__ float xin[INDIM];
    int t = threadIdx.x;

    int idx = (int)sol[(size_t)row * 4 + 0];
    xin[t] = emb[(size_t)idx * Cn + t];
    if (t == 0) {
        float rem = sol[(size_t)(b * Sn) * 4 + 3];
        float nd = (s == 0) ? 0.0f : 2.0f * (sol[(size_t)row * 4 + 2] - rem) / cap[b];
        xin[Cn] = nd;
    }
    __syncthreads();

    const float* W; const float* bb;
    if (s == 0)           { W = srcW;  bb = srcB;  }
    else if (s == Sn - 1) { W = depW;  bb = depB;  }
    else                  { W = candW; bb = candB; }

    int c = t;
    float acc0 = bb[c], acc1 = bb[c + 256];
    #pragma unroll 4
    for (int k = 0; k < INDIM; k++) {
        float xv = xin[k];
        acc0 += xv * W[k * Dn + c];
        acc1 += xv * W[k * Dn + c + 256];
    }
    g_x[(size_t)row * Dn + c]       = acc0;
    g_x[(size_t)row * Dn + c + 256] = acc1;
}

// ============================================================
// feasibility head
// ============================================================
__global__ void feas_kernel(const float* __restrict__ fW,
                            const float* __restrict__ fB,
                            float* __restrict__ out)
{
    int s = blockIdx.x + 1;
    int b = blockIdx.y;
    const float* xr = g_x + (size_t)(b * Sn + s) * Dn;
    int t = threadIdx.x;
    float acc = 0.f;
    #pragma unroll 4
    for (int k = t; k < Dn; k += 128) acc += xr[k] * fW[k];
    __shared__ float red[128];
    red[t] = acc; __syncthreads();
    for (int o = 64; o > 0; o >>= 1) {
        if (t < o) red[t] += red[t + o];
        __syncthreads();
    }
    if (t == 0) out[OUT_FEAS_OFF + b * 510 + (s - 1)] = red[0] + fB[0];
}

// ============================================================
// pointer logits
// ============================================================
__global__ void logits_kernel(const float* __restrict__ pW,
                              const float* __restrict__ pB,
                              float* __restrict__ out)
{
    int s = blockIdx.x + 1;
    int b = blockIdx.y;
    const float* xr = g_x + (size_t)(b * Sn + s) * Dn;
    int t = threadIdx.x;
    float a0 = 0.f, a1 = 0.f;
    #pragma unroll 4
    for (int k = t; k < Dn; k += 128) {
        float xv = xr[k];
        a0 += xv * pW[k * 2 + 0];
        a1 += xv * pW[k * 2 + 1];
    }
    __shared__ float r0[128], r1[128];
    r0[t] = a0; r1[t] = a1; __syncthreads();
    for (int o = 64; o > 0; o >>= 1) {
        if (t < o) { r0[t] += r0[t + o]; r1[t] += r1[t + o]; }
        __syncthreads();
    }
    if (t == 0) {
        out[b * OUT_LOGITS_PER_B + (s - 1)]       = r0[0] + pB[0];
        out[b * OUT_LOGITS_PER_B + 510 + (s - 1)] = r1[0] + pB[1];
    }
}

// ============================================================
// host orchestration
// ============================================================
extern "C" void kernel_launch(void* const* d_in, const int* in_sizes, int n_in,
                              void* d_out, int out_size)
{
    const float* sol   = (const float*)d_in[0];
    const float* cap   = (const float*)d_in[1];
    const float* emb   = (const float*)d_in[2];
    const float* srcW  = (const float*)d_in[3];
    const float* srcB  = (const float*)d_in[4];
    const float* candW = (const float*)d_in[5];
    const float* candB = (const float*)d_in[6];
    const float* depW  = (const float*)d_in[7];
    const float* depB  = (const float*)d_in[8];
    const float* feasW = (const float*)d_in[9];
    const float* feasB = (const float*)d_in[10];
    const float* Wq    = (const float*)d_in[11];
    const float* bq    = (const float*)d_in[12];
    const float* Wk    = (const float*)d_in[13];
    const float* bk    = (const float*)d_in[14];
    const float* Wv    = (const float*)d_in[15];
    const float* bv    = (const float*)d_in[16];
    const float* Wo    = (const float*)d_in[17];
    const float* bo    = (const float*)d_in[18];
    // d_in[19] = s_scale : softmax-shift-invariant, unused
    const float* W1    = (const float*)d_in[20];
    const float* b1    = (const float*)d_in[21];
    const float* W2    = (const float*)d_in[22];
    const float* b2    = (const float*)d_in[23];
    const float* ptrW  = (const float*)d_in[24];
    const float* ptrB  = (const float*)d_in[25];
    float* out = (float*)d_out;
    (void)in_sizes; (void)n_in; (void)out_size;

    float *px, *pq, *pk, *patt, *pvT, *ph;
    float *pwqkvT, *pbqkv, *pwoT, *pw1T, *pw2T;
    cudaGetSymbolAddress((void**)&px,     g_x);
    cudaGetSymbolAddress((void**)&pq,     g_q);
    cudaGetSymbolAddress((void**)&pk,     g_k);
    cudaGetSymbolAddress((void**)&patt,   g_att);
    cudaGetSymbolAddress((void**)&pvT,    g_vT);
    cudaGetSymbolAddress((void**)&ph,     g_h);
    cudaGetSymbolAddress((void**)&pwqkvT, g_wqkvT);
    cudaGetSymbolAddress((void**)&pbqkv,  g_bqkv);
    cudaGetSymbolAddress((void**)&pwoT,   g_woT);
    cudaGetSymbolAddress((void**)&pw1T,   g_w1T);
    cudaGetSymbolAddress((void**)&pw2T,   g_w2T);

    const int SM8 = (128 + 3 * (128 + 128) * 32) * 4;   // 98816
    const int SM4 = ( 64 + 3 * (128 +  64) * 32) * 4;   // 73984
    cudaFuncSetAttribute(mma_gemm<8, false, false, true >, cudaFuncAttributeMaxDynamicSharedMemorySize, SM8);
    cudaFuncSetAttribute(mma_gemm<8, true,  false, false>, cudaFuncAttributeMaxDynamicSharedMemorySize, SM8);
    cudaFuncSetAttribute(mma_gemm<4, false, true,  false>, cudaFuncAttributeMaxDynamicSharedMemorySize, SM4);
    cudaFuncSetAttribute(flash_kernel, cudaFuncAttributeMaxDynamicSharedMemorySize, FLASH_SMEM);

    const size_t DD = (size_t)Dn * Dn;           // 262144
    const size_t DH = (size_t)Dn * HIDn;         // 1048576
    const size_t QKVS = (size_t)1536 * Dn;       // 786432

    // ---- pack weights: QKV concat [1536,512], others [N,K] ----
    dim3 tb(32, 8);
    transpose_kernel<<<dim3(16, 16, Ln), tb>>>(Wq, pwqkvT, Dn, Dn, QKVS, 0);
    transpose_kernel<<<dim3(16, 16, Ln), tb>>>(Wk, pwqkvT, Dn, Dn, QKVS, DD);
    transpose_kernel<<<dim3(16, 16, Ln), tb>>>(Wv, pwqkvT, Dn, Dn, QKVS, 2 * DD);
    transpose_kernel<<<dim3(16, 16, Ln), tb>>>(Wo, pwoT, Dn, Dn, DD, 0);
    transpose_kernel<<<dim3(64, 16, Ln), tb>>>(W1, pw1T, Dn, HIDn, DH, 0);
    transpose_kernel<<<dim3(16, 64, Ln), tb>>>(W2, pw2T, HIDn, Dn, DH, 0);
    packbias_kernel<<<Ln, 512>>>(bq, bk, bv, pbqkv);

    build_x_kernel<<<Mn, 256>>>(sol, cap, emb, srcW, srcB, candW, candB, depW, depB);

    const dim3 gQKV(12, 32, 1);     // 384 CTAs
    const dim3 gP4 (8, 32, 1);      // 256 CTAs (BN=64)
    const dim3 gFF1(16, 32, 1);     // 512 CTAs
    const dim3 gFl (4, 64, 1);      // 256 CTAs

    for (int i = 0; i < Ln; i++) {
        // ---- fused QKV projection (outputs tf32 bits; V per-head-transposed) ----
        mma_gemm<8, false, false, true><<<gQKV, 128, SM8>>>(
            px, Dn, 0, 0,  pwqkvT + i * QKVS, Dn, 0, 0,  pq, Dn, 0, 0,
            pbqkv + i * 1536, nullptr, 1.0f, Dn, 1, pk, pvT);

        // ---- flash attention (scores+softmax+AV fused; +s*log(n) invariant) ----
        flash_kernel<<<gFl, 256, FLASH_SMEM>>>();

        // ---- O projection + residual ----
        mma_gemm<4, false, true, false><<<gP4, 128, SM4>>>(
            patt, Dn, 0, 0,  pwoT + i * DD, Dn, 0, 0,  px, Dn, 0, 0,
            bo + i * Dn, px, 1.0f, Dn, 1, nullptr, nullptr);

        // feasibility head reads x right after layer-0 attention residual
        if (i == 0)
            feas_kernel<<<dim3(510, Bn), 128>>>(feasW, feasB, out);

        // ---- FFN ----
        mma_gemm<8, true, false, false><<<gFF1, 128, SM8>>>(
            px, Dn, 0, 0,  pw1T + i * DH, Dn, 0, 0,  ph, HIDn, 0, 0,
            b1 + i * HIDn, nullptr, 1.0f, Dn, 1, nullptr, nullptr);
        mma_gemm<4, false, true, false><<<gP4, 128, SM4>>>(
            ph, HIDn, 0, 0,  pw2T + i * DH, HIDn, 0, 0,  px, Dn, 0, 0,
            b2 + i * Dn, px, 1.0f, HIDn, 1, nullptr, nullptr);
    }

    logits_kernel<<<dim3(510, Bn), 128>>>(ptrW, ptrB, out);
}

// round 6
// speedup vs baseline: 3.9933x; 1.0912x over previous
#include <cuda_runtime.h>
#include <cstdint>

// ---------------- problem constants ----------------
#define Bn   8
#define Sn   512
#define Ln   6
#define Dn   512
#define Hn   8
#define HDn  64
#define HIDn 2048
#define Cn   256
#define INDIM 257
#define Mn   (Bn * Sn)          // 4096 rows

#define OUT_LOGITS_PER_B 1020   // 2 * 510
#define OUT_FEAS_OFF     (Bn * OUT_LOGITS_PER_B)   // 8160

// ---------------- scratch (device globals; no allocation) ----------------
__device__ float g_x  [Mn * Dn];             // residual stream (fp32)
__device__ float g_xt [Mn * Dn];             // residual stream (tf32 bits)
__device__ float g_q  [Mn * Dn];             // Q (tf32 bits)
__device__ float g_k  [Mn * Dn];             // K (tf32 bits)
__device__ float g_att[Mn * Dn];             // attention out (tf32 bits)
__device__ float g_vT [Mn * Dn];             // V^T per head [b,h,e,s] (tf32 bits)
__device__ float g_h  [Mn * HIDn];           // FFN hidden (tf32 bits)
// transposed weights ([N,K] K-major, tf32 bits)
__device__ float g_wqkvT[Ln * 1536 * Dn];    // concat QKV [1536,512] per layer
__device__ float g_bqkv [Ln * 1536];
__device__ float g_woT[Ln * Dn * Dn];
__device__ float g_w1T[Ln * Dn * HIDn];
__device__ float g_w2T[Ln * HIDn * Dn];

// ============================================================
// portable PTX helpers
// ============================================================
__device__ __forceinline__ uint32_t su32(const void* p) {
    uint32_t a;
    asm("{ .reg .u64 t; cvta.to.shared.u64 t, %1; cvt.u32.u64 %0, t; }" : "=r"(a) : "l"(p));
    return a;
}
__device__ __forceinline__ void cp_async16(uint32_t s, const void* g) {
    asm volatile("cp.async.cg.shared.global [%0], [%1], 16;" :: "r"(s), "l"(g));
}
#define CP_COMMIT() asm volatile("cp.async.commit_group;" ::: "memory")
#define CP_WAIT(n)  asm volatile("cp.async.wait_group %0;" :: "n"(n) : "memory")

__device__ __forceinline__ uint32_t to_tf32(float f) {
    uint32_t r;
    asm("cvt.rna.tf32.f32 %0, %1;" : "=r"(r) : "f"(f));
    return r;
}
__device__ __forceinline__ float tf32f(float f) { return __uint_as_float(to_tf32(f)); }

#define MMA8(dd, af, b0, b1) \
    asm volatile("mma.sync.aligned.m16n8k8.row.col.f32.tf32.tf32.f32 " \
        "{%0,%1,%2,%3}, {%4,%5,%6,%7}, {%8,%9}, {%0,%1,%2,%3};" \
        : "+f"((dd)[0]), "+f"((dd)[1]), "+f"((dd)[2]), "+f"((dd)[3]) \
        : "r"((af)[0]), "r"((af)[1]), "r"((af)[2]), "r"((af)[3]), "r"(b0), "r"(b1))

// smem element index for [row][k] tile with 32-float rows, f4-XOR swizzle
__device__ __forceinline__ int swz(int row, int k) {
    return (((row << 3) + ((k >> 2) ^ (row & 7))) << 2) + (k & 3);
}

// ============================================================
// tf32 mma.sync GEMM: C = scale*(A B^T) (+bias, +Res, ReLU)
// All operands pre-rounded to tf32 bits -> NO cvt in mainloop.
// CTA 128 x (NT*16); BK=32; 3-stage cp.async; 128 threads.
// QKV: epilogue routes q/k/vT (tf32 bits). TOUT: C stored as tf32 bits.
// Ct (optional): tf32 shadow copy of C.
// ============================================================
template<int NT, bool RELU, bool RES, bool QKV, bool TOUT>
__global__ __launch_bounds__(128) void mma_gemm(
    const float* __restrict__ A, int lda,
    const float* __restrict__ B, int ldb,
    float* __restrict__ C, int ldc,
    const float* __restrict__ bias, const float* __restrict__ Res,
    float scale, int K,
    float* __restrict__ Ck, float* __restrict__ Cv, float* __restrict__ Ct)
{
    constexpr int BM = 128, BK = 32;
    constexpr int BN = NT * 16;
    constexpr int NSTAGE = 3;
    constexpr int STAGE_F = (BM + BN) * BK;

    extern __shared__ float smem[];
    float* sbias = smem;
    float* sdata = smem + BN;

    const int t = threadIdx.x;
    const int m0 = blockIdx.y * BM;
    const int n0 = blockIdx.x * BN;

    if (bias != nullptr && t < BN) sbias[t] = bias[n0 + t];

    auto load_stage = [&](int st, int k0) {
        float* sa = sdata + (st % NSTAGE) * STAGE_F;
        float* sb = sa + BM * BK;
        #pragma unroll
        for (int i = 0; i < 8; i++) {
            int j = t + 128 * i;
            int m = j >> 3, f = j & 7;
            uint32_t dst = su32(&sa[(((m << 3) + (f ^ (m & 7))) << 2)]);
            cp_async16(dst, A + (size_t)(m0 + m) * lda + k0 + (f << 2));
        }
        #pragma unroll
        for (int i = 0; i < BN / 16; i++) {
            int j = t + 128 * i;
            int n = j >> 3, f = j & 7;
            uint32_t dst = su32(&sb[(((n << 3) + (f ^ (n & 7))) << 2)]);
            cp_async16(dst, B + (size_t)(n0 + n) * ldb + k0 + (f << 2));
        }
        CP_COMMIT();
    };

    const int nst = K / BK;
    load_stage(0, 0);
    load_stage(1, BK);

    const int lane = t & 31, w = t >> 5;
    const int wm = w >> 1, wn = w & 1;
    const int g = lane >> 2, t4 = lane & 3;

    float d[4][NT][4] = {};

    for (int s = 0; s < nst; s++) {
        if (s < nst - 1) { CP_WAIT(1); } else { CP_WAIT(0); }
        __syncthreads();
        if (s + 2 < nst) load_stage(s + 2, (s + 2) * BK);

        const float* sa = sdata + (s % NSTAGE) * STAGE_F;
        const float* sb = sa + BM * BK;
        #pragma unroll
        for (int k8 = 0; k8 < 4; k8++) {
            const int kb = k8 << 3;
            uint32_t af[4][4];
            #pragma unroll
            for (int mt = 0; mt < 4; mt++) {
                int r = wm * 64 + mt * 16 + g;
                af[mt][0] = __float_as_uint(sa[swz(r,     kb + t4)]);
                af[mt][1] = __float_as_uint(sa[swz(r + 8, kb + t4)]);
                af[mt][2] = __float_as_uint(sa[swz(r,     kb + t4 + 4)]);
                af[mt][3] = __float_as_uint(sa[swz(r + 8, kb + t4 + 4)]);
            }
            #pragma unroll
            for (int nt = 0; nt < NT; nt++) {
                int n = wn * NT * 8 + nt * 8 + g;
                uint32_t b0 = __float_as_uint(sb[swz(n, kb + t4)]);
                uint32_t b1 = __float_as_uint(sb[swz(n, kb + t4 + 4)]);
                #pragma unroll
                for (int mt = 0; mt < 4; mt++) MMA8(d[mt][nt], af[mt], b0, b1);
            }
        }
    }

    // ---------------- epilogue ----------------
    const int colw = wn * NT * 8;
    #pragma unroll
    for (int mt = 0; mt < 4; mt++) {
        #pragma unroll
        for (int h2 = 0; h2 < 2; h2++) {
            const int m = m0 + wm * 64 + mt * 16 + g + h2 * 8;
            if (QKV) {
                const int region = n0 >> 9;       // 0=Q, 1=K, 2=V
                const int nb = n0 & 511;
                if (region < 2) {
                    float* crow = (region == 0 ? C : Ck) + (size_t)m * 512 + nb;
                    #pragma unroll
                    for (int nt = 0; nt < NT; nt++) {
                        int cl = colw + nt * 8 + 2 * t4;
                        float v0 = d[mt][nt][h2 * 2]     + sbias[cl];
                        float v1 = d[mt][nt][h2 * 2 + 1] + sbias[cl + 1];
                        *(float2*)(crow + cl) = make_float2(tf32f(v0), tf32f(v1));
                    }
                } else {
                    #pragma unroll
                    for (int nt = 0; nt < NT; nt++) {
                        int cl = colw + nt * 8 + 2 * t4;
                        float v0 = d[mt][nt][h2 * 2]     + sbias[cl];
                        float v1 = d[mt][nt][h2 * 2 + 1] + sbias[cl + 1];
                        int gc = nb + cl;
                        int hh = gc >> 6, e = gc & 63;
                        size_t base = ((size_t)((m >> 9) * Hn + hh) * 64 + e) * 512
                                      + (size_t)(m & 511);
                        Cv[base]       = tf32f(v0);
                        Cv[base + 512] = tf32f(v1);
                    }
                }
            } else {
                float* crow = C + (size_t)m * ldc + n0;
                float* trow = (Ct != nullptr) ? (Ct + (size_t)m * ldc + n0) : nullptr;
                const float* rrow = RES ? (Res + (size_t)m * ldc + n0) : nullptr;
                #pragma unroll
                for (int nt = 0; nt < NT; nt++) {
                    int cl = colw + nt * 8 + 2 * t4;
                    float v0 = d[mt][nt][h2 * 2]     * scale;
                    float v1 = d[mt][nt][h2 * 2 + 1] * scale;
                    if (bias != nullptr) { v0 += sbias[cl]; v1 += sbias[cl + 1]; }
                    if (RELU) { v0 = fmaxf(v0, 0.f); v1 = fmaxf(v1, 0.f); }
                    if (RES) {
                        float2 r = *(const float2*)(rrow + cl);
                        v0 += r.x; v1 += r.y;
                    }
                    if (TOUT) {
                        *(float2*)(crow + cl) = make_float2(tf32f(v0), tf32f(v1));
                    } else {
                        *(float2*)(crow + cl) = make_float2(v0, v1);
                    }
                    if (Ct != nullptr)
                        *(float2*)(trow + cl) = make_float2(tf32f(v0), tf32f(v1));
                }
            }
        }
    }
}

// ============================================================
// flash attention: per (b,h,qtile 128): online softmax, S never hits gmem
// 256 threads (8 warps); all operands tf32 bits; output tf32 bits.
// ============================================================
#define FLASH_SMEM 196608
#define NEG_INF (-1e30f)

__global__ __launch_bounds__(256) void flash_kernel()
{
    extern __shared__ float smem[];
    float* Ps = smem;                          // 16384 floats (P; Q staging)

    const int t = threadIdx.x;
    const int lane = t & 31, w = t >> 5;
    const int g = lane >> 2, t4 = lane & 3;
    const int q0 = blockIdx.x * 128;
    const int b = blockIdx.y >> 3, h = blockIdx.y & 7;
    const int r0 = w * 16;

    const float* qg = g_q  + (size_t)(b * Sn + q0) * Dn + h * HDn;
    const float* kg = g_k  + (size_t)(b * Sn) * Dn + h * HDn;
    const float* vg = g_vT + (size_t)(b * Hn + h) * HDn * Sn;

    #pragma unroll
    for (int i = 0; i < 8; i++) {
        int j = t + 256 * i;
        int r = j >> 4, f = j & 15;
        int ch = f >> 3, fc = f & 7;
        uint32_t dst = su32(&Ps[ch * 4096 + (((r << 3) + (fc ^ (r & 7))) << 2)]);
        cp_async16(dst, qg + (size_t)r * Dn + f * 4);
    }
    CP_COMMIT();

    auto load_kv = [&](int tile, int st) {
        float* kb = smem + 16384 + st * 16384;
        float* vb = kb + 8192;
        #pragma unroll
        for (int i = 0; i < 8; i++) {          // K tile [128 s][64 e]
            int j = t + 256 * i;
            int r = j >> 4, f = j & 15;
            int ch = f >> 3, fc = f & 7;
            uint32_t dst = su32(&kb[ch * 4096 + (((r << 3) + (fc ^ (r & 7))) << 2)]);
            cp_async16(dst, kg + (size_t)(tile * 128 + r) * Dn + f * 4);
        }
        #pragma unroll
        for (int i = 0; i < 8; i++) {          // V^T tile [64 e][128 s]
            int j = t + 256 * i;
            int e = j >> 5, f = j & 31;
            int ch = f >> 3, fc = f & 7;
            uint32_t dst = su32(&vb[ch * 2048 + (((e << 3) + (fc ^ (e & 7))) << 2)]);
            cp_async16(dst, vg + (size_t)e * Sn + tile * 128 + f * 4);
        }
        CP_COMMIT();
    };
    load_kv(0, 0);
    load_kv(1, 1);

    CP_WAIT(2);
    __syncthreads();
    uint32_t qf[8][4];
    #pragma unroll
    for (int c = 0; c < 2; c++)
        #pragma unroll
        for (int k8 = 0; k8 < 4; k8++) {
            const float* base = Ps + c * 4096;
            qf[c * 4 + k8][0] = __float_as_uint(base[swz(r0 + g,     k8 * 8 + t4)]);
            qf[c * 4 + k8][1] = __float_as_uint(base[swz(r0 + g + 8, k8 * 8 + t4)]);
            qf[c * 4 + k8][2] = __float_as_uint(base[swz(r0 + g,     k8 * 8 + t4 + 4)]);
            qf[c * 4 + k8][3] = __float_as_uint(base[swz(r0 + g + 8, k8 * 8 + t4 + 4)]);
        }
    __syncthreads();

    float m0 = NEG_INF, m1 = NEG_INF, l0 = 0.f, l1 = 0.f;
    float o[8][4] = {};

    for (int tile = 0; tile < 4; tile++) {
        if (tile < 3) { CP_WAIT(1); } else { CP_WAIT(0); }
        __syncthreads();
        const float* kb = smem + 16384 + (tile & 1) * 16384;
        const float* vb = kb + 8192;

        float s[16][4];
        #pragma unroll
        for (int nt = 0; nt < 16; nt++)
            #pragma unroll
            for (int j = 0; j < 4; j++) s[nt][j] = 0.f;
        #pragma unroll
        for (int c = 0; c < 2; c++)
            #pragma unroll
            for (int k8 = 0; k8 < 4; k8++) {
                const int kk = k8 * 8;
                #pragma unroll
                for (int nt = 0; nt < 16; nt++) {
                    uint32_t b0 = __float_as_uint(kb[c * 4096 + swz(nt * 8 + g, kk + t4)]);
                    uint32_t b1 = __float_as_uint(kb[c * 4096 + swz(nt * 8 + g, kk + t4 + 4)]);
                    MMA8(s[nt], qf[c * 4 + k8], b0, b1);
                }
            }

        float rm0 = NEG_INF, rm1 = NEG_INF;
        #pragma unroll
        for (int nt = 0; nt < 16; nt++) {
            s[nt][0] *= 0.125f; s[nt][1] *= 0.125f;
            s[nt][2] *= 0.125f; s[nt][3] *= 0.125f;
            rm0 = fmaxf(rm0, fmaxf(s[nt][0], s[nt][1]));
            rm1 = fmaxf(rm1, fmaxf(s[nt][2], s[nt][3]));
        }
        rm0 = fmaxf(rm0, __shfl_xor_sync(0xFFFFFFFF, rm0, 1));
        rm0 = fmaxf(rm0, __shfl_xor_sync(0xFFFFFFFF, rm0, 2));
        rm1 = fmaxf(rm1, __shfl_xor_sync(0xFFFFFFFF, rm1, 1));
        rm1 = fmaxf(rm1, __shfl_xor_sync(0xFFFFFFFF, rm1, 2));
        float mn0 = fmaxf(m0, rm0), mn1 = fmaxf(m1, rm1);
        float a0 = __expf(m0 - mn0), a1 = __expf(m1 - mn1);
        m0 = mn0; m1 = mn1;

        float rs0 = 0.f, rs1 = 0.f;
        #pragma unroll
        for (int nt = 0; nt < 16; nt++) {
            float p0 = __expf(s[nt][0] - m0);
            float p1 = __expf(s[nt][1] - m0);
            float p2 = __expf(s[nt][2] - m1);
            float p3 = __expf(s[nt][3] - m1);
            rs0 += p0 + p1; rs1 += p2 + p3;
            int col = nt * 8 + 2 * t4;
            int ch = col >> 5, kc = col & 31;
            *(float2*)&Ps[ch * 4096 + swz(r0 + g, kc)] = make_float2(tf32f(p0), tf32f(p1));
            *(float2*)&Ps[ch * 4096 + swz(r0 + g + 8, kc)] = make_float2(tf32f(p2), tf32f(p3));
        }
        rs0 += __shfl_xor_sync(0xFFFFFFFF, rs0, 1);
        rs0 += __shfl_xor_sync(0xFFFFFFFF, rs0, 2);
        rs1 += __shfl_xor_sync(0xFFFFFFFF, rs1, 1);
        rs1 += __shfl_xor_sync(0xFFFFFFFF, rs1, 2);
        l0 = l0 * a0 + rs0;
        l1 = l1 * a1 + rs1;
        #pragma unroll
        for (int nt = 0; nt < 8; nt++) {
            o[nt][0] *= a0; o[nt][1] *= a0;
            o[nt][2] *= a1; o[nt][3] *= a1;
        }
        __syncwarp();

        #pragma unroll
        for (int k8g = 0; k8g < 16; k8g++) {
            const int ch = k8g >> 2, kk = (k8g & 3) * 8;
            uint32_t af[4];
            af[0] = __float_as_uint(Ps[ch * 4096 + swz(r0 + g,     kk + t4)]);
            af[1] = __float_as_uint(Ps[ch * 4096 + swz(r0 + g + 8, kk + t4)]);
            af[2] = __float_as_uint(Ps[ch * 4096 + swz(r0 + g,     kk + t4 + 4)]);
            af[3] = __float_as_uint(Ps[ch * 4096 + swz(r0 + g + 8, kk + t4 + 4)]);
            #pragma unroll
            for (int nt = 0; nt < 8; nt++) {
                uint32_t b0 = __float_as_uint(vb[ch * 2048 + swz(nt * 8 + g, kk + t4)]);
                uint32_t b1 = __float_as_uint(vb[ch * 2048 + swz(nt * 8 + g, kk + t4 + 4)]);
                MMA8(o[nt], af, b0, b1);
            }
        }
        __syncthreads();
        if (tile + 2 < 4) load_kv(tile + 2, tile & 1);
    }

    // epilogue: O / l -> g_att (tf32 bits; consumed only by O-proj GEMM)
    float inv0 = 1.0f / l0, inv1 = 1.0f / l1;
    float* orow0 = g_att + (size_t)(b * Sn + q0 + r0 + g) * Dn + h * HDn;
    float* orow1 = orow0 + 8 * Dn;
    #pragma unroll
    for (int nt = 0; nt < 8; nt++) {
        int col = nt * 8 + 2 * t4;
        *(float2*)(orow0 + col) = make_float2(tf32f(o[nt][0] * inv0), tf32f(o[nt][1] * inv0));
        *(float2*)(orow1 + col) = make_float2(tf32f(o[nt][2] * inv1), tf32f(o[nt][3] * inv1));
    }
}

// ============================================================
// weight transpose -> tf32 bits: dst[zdst + c*R + r] = tf32(src[z][r][c])
// ============================================================
__global__ void transpose_kernel(const float* __restrict__ src, float* __restrict__ dst,
                                 int R, int C, size_t zstride, size_t doff)
{
    __shared__ float tile[32][33];
    size_t zsrc = (size_t)blockIdx.z * R * C;
    size_t zdst = (size_t)blockIdx.z * zstride + doff;
    int c0 = blockIdx.x * 32, r0 = blockIdx.y * 32;
    int tx = threadIdx.x, ty = threadIdx.y;       // 32 x 8
    #pragma unroll
    for (int j = 0; j < 32; j += 8)
        tile[ty + j][tx] = src[zsrc + (size_t)(r0 + ty + j) * C + c0 + tx];
    __syncthreads();
    #pragma unroll
    for (int j = 0; j < 32; j += 8)
        dst[zdst + (size_t)(c0 + ty + j) * R + r0 + tx] = tf32f(tile[tx][ty + j]);
}

__global__ void packbias_kernel(const float* __restrict__ bq, const float* __restrict__ bk,
                                const float* __restrict__ bv, float* __restrict__ dst)
{
    int i = blockIdx.x, t = threadIdx.x;   // Ln x 512
    dst[i * 1536 + t]        = bq[i * 512 + t];
    dst[i * 1536 + 512 + t]  = bk[i * 512 + t];
    dst[i * 1536 + 1024 + t] = bv[i * 512 + t];
}

// ============================================================
// build x = class_proj(concat(embed[idx], nd)); writes fp32 + tf32 shadow
// ============================================================
__global__ void build_x_kernel(const float* __restrict__ sol,
                               const float* __restrict__ cap,
                               const float* __restrict__ emb,
                               const float* __restrict__ srcW, const float* __restrict__ srcB,
                               const float* __restrict__ candW, const float* __restrict__ candB,
                               const float* __restrict__ depW, const float* __restrict__ depB)
{
    int row = blockIdx.x;
    int b = row / Sn, s = row % Sn;
    __shared__ float xin[INDIM];
    int t = threadIdx.x;

    int idx = (int)sol[(size_t)row * 4 + 0];
    xin[t] = emb[(size_t)idx * Cn + t];
    if (t == 0) {
        float rem = sol[(size_t)(b * Sn) * 4 + 3];
        float nd = (s == 0) ? 0.0f : 2.0f * (sol[(size_t)row * 4 + 2] - rem) / cap[b];
        xin[Cn] = nd;
    }
    __syncthreads();

    const float* W; const float* bb;
    if (s == 0)           { W = srcW;  bb = srcB;  }
    else if (s == Sn - 1) { W = depW;  bb = depB;  }
    else                  { W = candW; bb = candB; }

    int c = t;
    float acc0 = bb[c], acc1 = bb[c + 256];
    #pragma unroll 4
    for (int k = 0; k < INDIM; k++) {
        float xv = xin[k];
        acc0 += xv * W[k * Dn + c];
        acc1 += xv * W[k * Dn + c + 256];
    }
    g_x [(size_t)row * Dn + c]       = acc0;
    g_x [(size_t)row * Dn + c + 256] = acc1;
    g_xt[(size_t)row * Dn + c]       = tf32f(acc0);
    g_xt[(size_t)row * Dn + c + 256] = tf32f(acc1);
}

// ============================================================
// feasibility head
// ============================================================
__global__ void feas_kernel(const float* __restrict__ fW,
                            const float* __restrict__ fB,
                            float* __restrict__ out)
{
    int s = blockIdx.x + 1;
    int b = blockIdx.y;
    const float* xr = g_x + (size_t)(b * Sn + s) * Dn;
    int t = threadIdx.x;
    float acc = 0.f;
    #pragma unroll 4
    for (int k = t; k < Dn; k += 128) acc += xr[k] * fW[k];
    __shared__ float red[128];
    red[t] = acc; __syncthreads();
    for (int o = 64; o > 0; o >>= 1) {
        if (t < o) red[t] += red[t + o];
        __syncthreads();
    }
    if (t == 0) out[OUT_FEAS_OFF + b * 510 + (s - 1)] = red[0] + fB[0];
}

// ============================================================
// pointer logits
// ============================================================
__global__ void logits_kernel(const float* __restrict__ pW,
                              const float* __restrict__ pB,
                              float* __restrict__ out)
{
    int s = blockIdx.x + 1;
    int b = blockIdx.y;
    const float* xr = g_x + (size_t)(b * Sn + s) * Dn;
    int t = threadIdx.x;
    float a0 = 0.f, a1 = 0.f;
    #pragma unroll 4
    for (int k = t; k < Dn; k += 128) {
        float xv = xr[k];
        a0 += xv * pW[k * 2 + 0];
        a1 += xv * pW[k * 2 + 1];
    }
    __shared__ float r0[128], r1[128];
    r0[t] = a0; r1[t] = a1; __syncthreads();
    for (int o = 64; o > 0; o >>= 1) {
        if (t < o) { r0[t] += r0[t + o]; r1[t] += r1[t + o]; }
        __syncthreads();
    }
    if (t == 0) {
        out[b * OUT_LOGITS_PER_B + (s - 1)]       = r0[0] + pB[0];
        out[b * OUT_LOGITS_PER_B + 510 + (s - 1)] = r1[0] + pB[1];
    }
}

// ============================================================
// host orchestration
// ============================================================
extern "C" void kernel_launch(void* const* d_in, const int* in_sizes, int n_in,
                              void* d_out, int out_size)
{
    const float* sol   = (const float*)d_in[0];
    const float* cap   = (const float*)d_in[1];
    const float* emb   = (const float*)d_in[2];
    const float* srcW  = (const float*)d_in[3];
    const float* srcB  = (const float*)d_in[4];
    const float* candW = (const float*)d_in[5];
    const float* candB = (const float*)d_in[6];
    const float* depW  = (const float*)d_in[7];
    const float* depB  = (const float*)d_in[8];
    const float* feasW = (const float*)d_in[9];
    const float* feasB = (const float*)d_in[10];
    const float* Wq    = (const float*)d_in[11];
    const float* bq    = (const float*)d_in[12];
    const float* Wk    = (const float*)d_in[13];
    const float* bk    = (const float*)d_in[14];
    const float* Wv    = (const float*)d_in[15];
    const float* bv    = (const float*)d_in[16];
    const float* Wo    = (const float*)d_in[17];
    const float* bo    = (const float*)d_in[18];
    // d_in[19] = s_scale : softmax-shift-invariant, unused
    const float* W1    = (const float*)d_in[20];
    const float* b1    = (const float*)d_in[21];
    const float* W2    = (const float*)d_in[22];
    const float* b2    = (const float*)d_in[23];
    const float* ptrW  = (const float*)d_in[24];
    const float* ptrB  = (const float*)d_in[25];
    float* out = (float*)d_out;
    (void)in_sizes; (void)n_in; (void)out_size;

    float *px, *pxt, *pq, *pk, *patt, *pvT, *ph;
    float *pwqkvT, *pbqkv, *pwoT, *pw1T, *pw2T;
    cudaGetSymbolAddress((void**)&px,     g_x);
    cudaGetSymbolAddress((void**)&pxt,    g_xt);
    cudaGetSymbolAddress((void**)&pq,     g_q);
    cudaGetSymbolAddress((void**)&pk,     g_k);
    cudaGetSymbolAddress((void**)&patt,   g_att);
    cudaGetSymbolAddress((void**)&pvT,    g_vT);
    cudaGetSymbolAddress((void**)&ph,     g_h);
    cudaGetSymbolAddress((void**)&pwqkvT, g_wqkvT);
    cudaGetSymbolAddress((void**)&pbqkv,  g_bqkv);
    cudaGetSymbolAddress((void**)&pwoT,   g_woT);
    cudaGetSymbolAddress((void**)&pw1T,   g_w1T);
    cudaGetSymbolAddress((void**)&pw2T,   g_w2T);

    const int SM8 = (128 + 3 * (128 + 128) * 32) * 4;   // 98816
    const int SM4 = ( 64 + 3 * (128 +  64) * 32) * 4;   // 73984
    cudaFuncSetAttribute(mma_gemm<8, false, false, true,  false>, cudaFuncAttributeMaxDynamicSharedMemorySize, SM8);
    cudaFuncSetAttribute(mma_gemm<8, true,  false, false, true >, cudaFuncAttributeMaxDynamicSharedMemorySize, SM8);
    cudaFuncSetAttribute(mma_gemm<4, false, true,  false, false>, cudaFuncAttributeMaxDynamicSharedMemorySize, SM4);
    cudaFuncSetAttribute(flash_kernel, cudaFuncAttributeMaxDynamicSharedMemorySize, FLASH_SMEM);

    const size_t DD = (size_t)Dn * Dn;           // 262144
    const size_t DH = (size_t)Dn * HIDn;         // 1048576
    const size_t QKVS = (size_t)1536 * Dn;       // 786432

    // ---- pack weights (tf32 bits): QKV concat [1536,512], others [N,K] ----
    dim3 tb(32, 8);
    transpose_kernel<<<dim3(16, 16, Ln), tb>>>(Wq, pwqkvT, Dn, Dn, QKVS, 0);
    transpose_kernel<<<dim3(16, 16, Ln), tb>>>(Wk, pwqkvT, Dn, Dn, QKVS, DD);
    transpose_kernel<<<dim3(16, 16, Ln), tb>>>(Wv, pwqkvT, Dn, Dn, QKVS, 2 * DD);
    transpose_kernel<<<dim3(16, 16, Ln), tb>>>(Wo, pwoT, Dn, Dn, DD, 0);
    transpose_kernel<<<dim3(64, 16, Ln), tb>>>(W1, pw1T, Dn, HIDn, DH, 0);
    transpose_kernel<<<dim3(16, 64, Ln), tb>>>(W2, pw2T, HIDn, Dn, DH, 0);
    packbias_kernel<<<Ln, 512>>>(bq, bk, bv, pbqkv);

    build_x_kernel<<<Mn, 256>>>(sol, cap, emb, srcW, srcB, candW, candB, depW, depB);

    const dim3 gQKV(12, 32, 1);     // 384 CTAs
    const dim3 gP4 (8, 32, 1);      // 256 CTAs (BN=64)
    const dim3 gFF1(16, 32, 1);     // 512 CTAs
    const dim3 gFl (4, 64, 1);      // 256 CTAs

    for (int i = 0; i < Ln; i++) {
        // ---- fused QKV projection (tf32-bit outputs; V per-head-transposed) ----
        mma_gemm<8, false, false, true, false><<<gQKV, 128, SM8>>>(
            pxt, Dn,  pwqkvT + i * QKVS, Dn,  pq, Dn,
            pbqkv + i * 1536, nullptr, 1.0f, Dn, pk, pvT, nullptr);

        // ---- flash attention ----
        flash_kernel<<<gFl, 256, FLASH_SMEM>>>();

        // ---- O projection + residual (writes x fp32 + xt tf32) ----
        mma_gemm<4, false, true, false, false><<<gP4, 128, SM4>>>(
            patt, Dn,  pwoT + i * DD, Dn,  px, Dn,
            bo + i * Dn, px, 1.0f, Dn, nullptr, nullptr, pxt);

        if (i == 0)
            feas_kernel<<<dim3(510, Bn), 128>>>(feasW, feasB, out);

        // ---- FFN (h stored as tf32 bits) ----
        mma_gemm<8, true, false, false, true><<<gFF1, 128, SM8>>>(
            pxt, Dn,  pw1T + i * DH, Dn,  ph, HIDn,
            b1 + i * HIDn, nullptr, 1.0f, Dn, nullptr, nullptr, nullptr);
        mma_gemm<4, false, true, false, false><<<gP4, 128, SM4>>>(
            ph, HIDn,  pw2T + i * DH, HIDn,  px, Dn,
            b2 + i * Dn, px, 1.0f, HIDn, nullptr, nullptr, pxt);
    }

    logits_kernel<<<dim3(510, Bn), 128>>>(ptrW, ptrB, out);
}

// round 8
// speedup vs baseline: 6.4128x; 1.6059x over previous
#include <cuda_runtime.h>
#include <cuda_fp16.h>
#include <cstdint>

// ---------------- problem constants ----------------
#define Bn   8
#define Sn   512
#define Ln   6
#define Dn   512
#define Hn   8
#define HDn  64
#define HIDn 2048
#define Cn   256
#define INDIM 257
#define Mn   (Bn * Sn)          // 4096 rows

#define OUT_LOGITS_PER_B 1020   // 2 * 510
#define OUT_FEAS_OFF     (Bn * OUT_LOGITS_PER_B)   // 8160

// ---------------- scratch (device globals; no allocation) ----------------
__device__ float  g_x  [Mn * Dn];            // residual stream (fp32)
__device__ __half g_xt [Mn * Dn];            // residual stream (fp16)
__device__ __half g_q  [Mn * Dn];            // Q (fp16)
__device__ __half g_k  [Mn * Dn];            // K (fp16)
__device__ __half g_att[Mn * Dn];            // attention out (fp16)
__device__ __half g_vT [Mn * Dn];            // V^T per head [b,h,e,s] (fp16)
__device__ __half g_h  [Mn * HIDn];          // FFN hidden (fp16)
// transposed weights ([N,K] K-major, fp16)
__device__ __half g_wqkvT[Ln * 1536 * Dn];   // concat QKV [1536,512] per layer
__device__ float  g_bqkv [Ln * 1536];
__device__ __half g_woT[Ln * Dn * Dn];
__device__ __half g_w1T[Ln * Dn * HIDn];
__device__ __half g_w2T[Ln * HIDn * Dn];

// ============================================================
// portable PTX helpers
// ============================================================
__device__ __forceinline__ uint32_t su32(const void* p) {
    uint32_t a;
    asm("{ .reg .u64 t; cvta.to.shared.u64 t, %1; cvt.u32.u64 %0, t; }" : "=r"(a) : "l"(p));
    return a;
}
__device__ __forceinline__ void cp_async16(uint32_t s, const void* g) {
    asm volatile("cp.async.cg.shared.global [%0], [%1], 16;" :: "r"(s), "l"(g));
}
#define CP_COMMIT() asm volatile("cp.async.commit_group;" ::: "memory")
#define CP_WAIT(n)  asm volatile("cp.async.wait_group %0;" :: "n"(n) : "memory")

// fp16 mma: D(f32) += A(f16) B(f16)^T ; A=4 regs (8 halves), B=2 regs (4 halves)
#define MMA16(dd, af, b0, b1) \
    asm volatile("mma.sync.aligned.m16n8k16.row.col.f32.f16.f16.f32 " \
        "{%0,%1,%2,%3}, {%4,%5,%6,%7}, {%8,%9}, {%0,%1,%2,%3};" \
        : "+f"((dd)[0]), "+f"((dd)[1]), "+f"((dd)[2]), "+f"((dd)[3]) \
        : "r"((af)[0]), "r"((af)[1]), "r"((af)[2]), "r"((af)[3]), "r"(b0), "r"(b1))

// half-element index in a [row][64-half] tile (128B rows, 16B-chunk XOR swizzle)
__device__ __forceinline__ int swzh(int row, int k) {
    return (row << 6) + ((((k >> 3) ^ row) & 7) << 3) + (k & 7);
}
__device__ __forceinline__ uint32_t ldsu(const __half* p) {
    return *(const uint32_t*)p;
}

// ============================================================
// fp16 mma.sync GEMM: C = scale*(A B^T) (+bias, +Res, ReLU)
// CTA 128 x (NT*16); BK=64 halves; 3-stage cp.async; 128 threads.
// QKV: epilogue routes q/k/vT (fp16). TOUT: C is fp16. Ct: fp16 shadow of C.
// ============================================================
template<int NT, bool RELU, bool RES, bool QKV, bool TOUT>
__global__ __launch_bounds__(128) void mma_gemm(
    const __half* __restrict__ A, int lda,
    const __half* __restrict__ B, int ldb,
    void* __restrict__ Cp, int ldc,
    const float* __restrict__ bias, const float* __restrict__ Res,
    float scale, int K,
    __half* __restrict__ Ck, __half* __restrict__ Cv, __half* __restrict__ Ct)
{
    constexpr int BM = 128, BK = 64;
    constexpr int BN = NT * 16;
    constexpr int NSTAGE = 3;
    constexpr int STAGE_H = (BM + BN) * BK;      // halves per stage

    extern __shared__ float smem[];
    float* sbias = smem;
    __half* sdata = (__half*)(smem + BN);

    const int t = threadIdx.x;
    const int m0 = blockIdx.y * BM;
    const int n0 = blockIdx.x * BN;

    if (bias != nullptr && t < BN) sbias[t] = bias[n0 + t];

    auto load_stage = [&](int st, int k0) {
        __half* sa = sdata + (st % NSTAGE) * STAGE_H;
        __half* sb = sa + BM * BK;
        #pragma unroll
        for (int i = 0; i < 8; i++) {             // A: 128 rows x 8 chunks
            int j = t + 128 * i;
            int m = j >> 3, f = j & 7;
            uint32_t dst = su32(&sa[(m << 6) + (((f ^ m) & 7) << 3)]);
            cp_async16(dst, A + (size_t)(m0 + m) * lda + k0 + (f << 3));
        }
        #pragma unroll
        for (int i = 0; i < NT; i++) {            // B: BN rows x 8 chunks (BN*8/128 = NT iters)
            int j = t + 128 * i;
            int n = j >> 3, f = j & 7;
            uint32_t dst = su32(&sb[(n << 6) + (((f ^ n) & 7) << 3)]);
            cp_async16(dst, B + (size_t)(n0 + n) * ldb + k0 + (f << 3));
        }
        CP_COMMIT();
    };

    const int nst = K / BK;
    load_stage(0, 0);
    load_stage(1, BK);

    const int lane = t & 31, w = t >> 5;
    const int wm = w >> 1, wn = w & 1;
    const int g = lane >> 2, t4 = lane & 3;

    float d[4][NT][4] = {};

    for (int s = 0; s < nst; s++) {
        if (s < nst - 1) { CP_WAIT(1); } else { CP_WAIT(0); }
        __syncthreads();
        if (s + 2 < nst) load_stage(s + 2, (s + 2) * BK);

        const __half* sa = sdata + (s % NSTAGE) * STAGE_H;
        const __half* sb = sa + BM * BK;
        #pragma unroll
        for (int k16 = 0; k16 < 4; k16++) {
            const int kb = k16 << 4;
            uint32_t af[4][4];
            #pragma unroll
            for (int mt = 0; mt < 4; mt++) {
                int r = wm * 64 + mt * 16 + g;
                af[mt][0] = ldsu(&sa[swzh(r,     kb + 2 * t4)]);
                af[mt][1] = ldsu(&sa[swzh(r + 8, kb + 2 * t4)]);
                af[mt][2] = ldsu(&sa[swzh(r,     kb + 8 + 2 * t4)]);
                af[mt][3] = ldsu(&sa[swzh(r + 8, kb + 8 + 2 * t4)]);
            }
            #pragma unroll
            for (int nt = 0; nt < NT; nt++) {
                int n = wn * NT * 8 + nt * 8 + g;
                uint32_t b0 = ldsu(&sb[swzh(n, kb + 2 * t4)]);
                uint32_t b1 = ldsu(&sb[swzh(n, kb + 8 + 2 * t4)]);
                #pragma unroll
                for (int mt = 0; mt < 4; mt++) MMA16(d[mt][nt], af[mt], b0, b1);
            }
        }
    }

    // ---------------- epilogue ----------------
    const int colw = wn * NT * 8;
    #pragma unroll
    for (int mt = 0; mt < 4; mt++) {
        #pragma unroll
        for (int h2 = 0; h2 < 2; h2++) {
            const int m = m0 + wm * 64 + mt * 16 + g + h2 * 8;
            if (QKV) {
                const int region = n0 >> 9;       // 0=Q, 1=K, 2=V
                const int nb = n0 & 511;
                if (region < 2) {
                    __half* crow = (region == 0 ? (__half*)Cp : Ck) + (size_t)m * 512 + nb;
                    #pragma unroll
                    for (int nt = 0; nt < NT; nt++) {
                        int cl = colw + nt * 8 + 2 * t4;
                        float v0 = d[mt][nt][h2 * 2]     + sbias[cl];
                        float v1 = d[mt][nt][h2 * 2 + 1] + sbias[cl + 1];
                        *(__half2*)(crow + cl) = __floats2half2_rn(v0, v1);
                    }
                } else {
                    #pragma unroll
                    for (int nt = 0; nt < NT; nt++) {
                        int cl = colw + nt * 8 + 2 * t4;
                        float v0 = d[mt][nt][h2 * 2]     + sbias[cl];
                        float v1 = d[mt][nt][h2 * 2 + 1] + sbias[cl + 1];
                        int gc = nb + cl;
                        int hh = gc >> 6, e = gc & 63;
                        size_t base = ((size_t)((m >> 9) * Hn + hh) * 64 + e) * 512
                                      + (size_t)(m & 511);
                        Cv[base]       = __float2half_rn(v0);
                        Cv[base + 512] = __float2half_rn(v1);
                    }
                }
            } else if (TOUT) {
                __half* crow = (__half*)Cp + (size_t)m * ldc + n0;
                #pragma unroll
                for (int nt = 0; nt < NT; nt++) {
                    int cl = colw + nt * 8 + 2 * t4;
                    float v0 = d[mt][nt][h2 * 2]     + sbias[cl];
                    float v1 = d[mt][nt][h2 * 2 + 1] + sbias[cl + 1];
                    if (RELU) { v0 = fmaxf(v0, 0.f); v1 = fmaxf(v1, 0.f); }
                    *(__half2*)(crow + cl) = __floats2half2_rn(v0, v1);
                }
            } else {
                float* crow = (float*)Cp + (size_t)m * ldc + n0;
                __half* trow = (Ct != nullptr) ? (Ct + (size_t)m * ldc + n0) : nullptr;
                const float* rrow = RES ? (Res + (size_t)m * ldc + n0) : nullptr;
                #pragma unroll
                for (int nt = 0; nt < NT; nt++) {
                    int cl = colw + nt * 8 + 2 * t4;
                    float v0 = d[mt][nt][h2 * 2]     * scale;
                    float v1 = d[mt][nt][h2 * 2 + 1] * scale;
                    if (bias != nullptr) { v0 += sbias[cl]; v1 += sbias[cl + 1]; }
                    if (RELU) { v0 = fmaxf(v0, 0.f); v1 = fmaxf(v1, 0.f); }
                    if (RES) {
                        float2 r = *(const float2*)(rrow + cl);
                        v0 += r.x; v1 += r.y;
                    }
                    *(float2*)(crow + cl) = make_float2(v0, v1);
                    if (Ct != nullptr)
                        *(__half2*)(trow + cl) = __floats2half2_rn(v0, v1);
                }
            }
        }
    }
}

// ============================================================
// flash attention (fp16 operands, fp32 accum/softmax)
// per (b,h,qtile 128); 256 threads; smem 96KB:
//   Ps: P/Q staging 2 x [128][64] halves (32KB)
//   2 stages x (K [128][64] + V^T 2x[64][64]) halves (2 x 32KB)
// ============================================================
#define FLASH_SMEM 98304
#define NEG_INF (-1e30f)

__global__ __launch_bounds__(256) void flash_kernel()
{
    extern __shared__ __half smh[];
    __half* Ps = smh;                          // 16384 halves

    const int t = threadIdx.x;
    const int lane = t & 31, w = t >> 5;
    const int g = lane >> 2, t4 = lane & 3;
    const int q0 = blockIdx.x * 128;
    const int b = blockIdx.y >> 3, h = blockIdx.y & 7;
    const int r0 = w * 16;

    const __half* qg = g_q  + (size_t)(b * Sn + q0) * Dn + h * HDn;
    const __half* kg = g_k  + (size_t)(b * Sn) * Dn + h * HDn;
    const __half* vg = g_vT + (size_t)(b * Hn + h) * HDn * Sn;

    // ---- stage Q into Ps chunk0: [128 q][64 e] ----
    #pragma unroll
    for (int i = 0; i < 4; i++) {
        int j = t + 256 * i;
        int r = j >> 3, f = j & 7;
        uint32_t dst = su32(&Ps[(r << 6) + (((f ^ r) & 7) << 3)]);
        cp_async16(dst, qg + (size_t)r * Dn + (f << 3));
    }
    CP_COMMIT();

    auto load_kv = [&](int tile, int st) {
        __half* kb = smh + 16384 + st * 16384;
        __half* vb = kb + 8192;
        #pragma unroll
        for (int i = 0; i < 4; i++) {          // K tile [128 s][64 e]
            int j = t + 256 * i;
            int r = j >> 3, f = j & 7;
            uint32_t dst = su32(&kb[(r << 6) + (((f ^ r) & 7) << 3)]);
            cp_async16(dst, kg + (size_t)(tile * 128 + r) * Dn + (f << 3));
        }
        #pragma unroll
        for (int i = 0; i < 4; i++) {          // V^T tile [64 e][128 s] -> 2 chunks
            int j = t + 256 * i;
            int e = j >> 4, f = j & 15;
            int ss = f >> 3, fc = f & 7;
            uint32_t dst = su32(&vb[ss * 4096 + (e << 6) + (((fc ^ e) & 7) << 3)]);
            cp_async16(dst, vg + (size_t)e * Sn + tile * 128 + (f << 3));
        }
        CP_COMMIT();
    };
    load_kv(0, 0);
    load_kv(1, 1);

    // ---- Q fragments (held in regs) ----
    CP_WAIT(2);
    __syncthreads();
    uint32_t qf[4][4];
    #pragma unroll
    for (int k16 = 0; k16 < 4; k16++) {
        const int kb = k16 << 4;
        qf[k16][0] = ldsu(&Ps[swzh(r0 + g,     kb + 2 * t4)]);
        qf[k16][1] = ldsu(&Ps[swzh(r0 + g + 8, kb + 2 * t4)]);
        qf[k16][2] = ldsu(&Ps[swzh(r0 + g,     kb + 8 + 2 * t4)]);
        qf[k16][3] = ldsu(&Ps[swzh(r0 + g + 8, kb + 8 + 2 * t4)]);
    }
    __syncthreads();

    float m0 = NEG_INF, m1 = NEG_INF, l0 = 0.f, l1 = 0.f;
    float o[8][4] = {};

    for (int tile = 0; tile < 4; tile++) {
        if (tile < 3) { CP_WAIT(1); } else { CP_WAIT(0); }
        __syncthreads();
        const __half* kb = smh + 16384 + (tile & 1) * 16384;
        const __half* vb = kb + 8192;

        // ---- S = Q K^T ----
        float s[16][4];
        #pragma unroll
        for (int nt = 0; nt < 16; nt++)
            #pragma unroll
            for (int j = 0; j < 4; j++) s[nt][j] = 0.f;
        #pragma unroll
        for (int k16 = 0; k16 < 4; k16++) {
            const int kk = k16 << 4;
            #pragma unroll
            for (int nt = 0; nt < 16; nt++) {
                uint32_t b0 = ldsu(&kb[swzh(nt * 8 + g, kk + 2 * t4)]);
                uint32_t b1 = ldsu(&kb[swzh(nt * 8 + g, kk + 8 + 2 * t4)]);
                MMA16(s[nt], qf[k16], b0, b1);
            }
        }

        // ---- online softmax update ----
        float rm0 = NEG_INF, rm1 = NEG_INF;
        #pragma unroll
        for (int nt = 0; nt < 16; nt++) {
            s[nt][0] *= 0.125f; s[nt][1] *= 0.125f;
            s[nt][2] *= 0.125f; s[nt][3] *= 0.125f;
            rm0 = fmaxf(rm0, fmaxf(s[nt][0], s[nt][1]));
            rm1 = fmaxf(rm1, fmaxf(s[nt][2], s[nt][3]));
        }
        rm0 = fmaxf(rm0, __shfl_xor_sync(0xFFFFFFFF, rm0, 1));
        rm0 = fmaxf(rm0, __shfl_xor_sync(0xFFFFFFFF, rm0, 2));
        rm1 = fmaxf(rm1, __shfl_xor_sync(0xFFFFFFFF, rm1, 1));
        rm1 = fmaxf(rm1, __shfl_xor_sync(0xFFFFFFFF, rm1, 2));
        float mn0 = fmaxf(m0, rm0), mn1 = fmaxf(m1, rm1);
        float a0 = __expf(m0 - mn0), a1 = __expf(m1 - mn1);
        m0 = mn0; m1 = mn1;

        float rs0 = 0.f, rs1 = 0.f;
        #pragma unroll
        for (int nt = 0; nt < 16; nt++) {
            float p0 = __expf(s[nt][0] - m0);
            float p1 = __expf(s[nt][1] - m0);
            float p2 = __expf(s[nt][2] - m1);
            float p3 = __expf(s[nt][3] - m1);
            rs0 += p0 + p1; rs1 += p2 + p3;
            int col = nt * 8 + 2 * t4;
            int ch = col >> 6, kc = col & 63;
            *(__half2*)&Ps[ch * 8192 + swzh(r0 + g, kc)]     = __floats2half2_rn(p0, p1);
            *(__half2*)&Ps[ch * 8192 + swzh(r0 + g + 8, kc)] = __floats2half2_rn(p2, p3);
        }
        rs0 += __shfl_xor_sync(0xFFFFFFFF, rs0, 1);
        rs0 += __shfl_xor_sync(0xFFFFFFFF, rs0, 2);
        rs1 += __shfl_xor_sync(0xFFFFFFFF, rs1, 1);
        rs1 += __shfl_xor_sync(0xFFFFFFFF, rs1, 2);
        l0 = l0 * a0 + rs0;
        l1 = l1 * a1 + rs1;
        #pragma unroll
        for (int nt = 0; nt < 8; nt++) {
            o[nt][0] *= a0; o[nt][1] *= a0;
            o[nt][2] *= a1; o[nt][3] *= a1;
        }
        __syncwarp();

        // ---- O += P @ V^T ----
        #pragma unroll
        for (int ks = 0; ks < 8; ks++) {
            const int ch = ks >> 2, kk = (ks << 4) & 63;
            uint32_t af[4];
            af[0] = ldsu(&Ps[ch * 8192 + swzh(r0 + g,     kk + 2 * t4)]);
            af[1] = ldsu(&Ps[ch * 8192 + swzh(r0 + g + 8, kk + 2 * t4)]);
            af[2] = ldsu(&Ps[ch * 8192 + swzh(r0 + g,     kk + 8 + 2 * t4)]);
            af[3] = ldsu(&Ps[ch * 8192 + swzh(r0 + g + 8, kk + 8 + 2 * t4)]);
            #pragma unroll
            for (int nt = 0; nt < 8; nt++) {
                uint32_t b0 = ldsu(&vb[ch * 4096 + swzh(nt * 8 + g, kk + 2 * t4)]);
                uint32_t b1 = ldsu(&vb[ch * 4096 + swzh(nt * 8 + g, kk + 8 + 2 * t4)]);
                MMA16(o[nt], af, b0, b1);
            }
        }
        __syncthreads();
        if (tile + 2 < 4) load_kv(tile + 2, tile & 1);
    }

    // ---- epilogue: O / l -> g_att (fp16) ----
    float inv0 = 1.0f / l0, inv1 = 1.0f / l1;
    __half* orow0 = g_att + (size_t)(b * Sn + q0 + r0 + g) * Dn + h * HDn;
    __half* orow1 = orow0 + 8 * Dn;
    #pragma unroll
    for (int nt = 0; nt < 8; nt++) {
        int col = nt * 8 + 2 * t4;
        *(__half2*)(orow0 + col) = __floats2half2_rn(o[nt][0] * inv0, o[nt][1] * inv0);
        *(__half2*)(orow1 + col) = __floats2half2_rn(o[nt][2] * inv1, o[nt][3] * inv1);
    }
}

// ============================================================
// weight transpose -> fp16: dst[zdst + c*R + r] = h(src[z][r][c])
// ============================================================
__global__ void transpose_kernel(const float* __restrict__ src, __half* __restrict__ dst,
                                 int R, int C, size_t zstride, size_t doff)
{
    __shared__ float tile[32][33];
    size_t zsrc = (size_t)blockIdx.z * R * C;
    size_t zdst = (size_t)blockIdx.z * zstride + doff;
    int c0 = blockIdx.x * 32, r0 = blockIdx.y * 32;
    int tx = threadIdx.x, ty = threadIdx.y;       // 32 x 8
    #pragma unroll
    for (int j = 0; j < 32; j += 8)
        tile[ty + j][tx] = src[zsrc + (size_t)(r0 + ty + j) * C + c0 + tx];
    __syncthreads();
    #pragma unroll
    for (int j = 0; j < 32; j += 8)
        dst[zdst + (size_t)(c0 + ty + j) * R + r0 + tx] = __float2half_rn(tile[tx][ty + j]);
}

__global__ void packbias_kernel(const float* __restrict__ bq, const float* __restrict__ bk,
                                const float* __restrict__ bv, float* __restrict__ dst)
{
    int i = blockIdx.x, t = threadIdx.x;   // Ln x 512
    dst[i * 1536 + t]        = bq[i * 512 + t];
    dst[i * 1536 + 512 + t]  = bk[i * 512 + t];
    dst[i * 1536 + 1024 + t] = bv[i * 512 + t];
}

// ============================================================
// build x = class_proj(concat(embed[idx], nd)); writes fp32 + fp16 shadow
// ============================================================
__global__ void build_x_kernel(const float* __restrict__ sol,
                               const float* __restrict__ cap,
                               const float* __restrict__ emb,
                               const float* __restrict__ srcW, const float* __restrict__ srcB,
                               const float* __restrict__ candW, const float* __restrict__ candB,
                               const float* __restrict__ depW, const float* __restrict__ depB)
{
    int row = blockIdx.x;
    int b = row / Sn, s = row % Sn;
    __shared__ float xin[INDIM];
    int t = threadIdx.x;

    int idx = (int)sol[(size_t)row * 4 + 0];
    xin[t] = emb[(size_t)idx * Cn + t];
    if (t == 0) {
        float rem = sol[(size_t)(b * Sn) * 4 + 3];
        float nd = (s == 0) ? 0.0f : 2.0f * (sol[(size_t)row * 4 + 2] - rem) / cap[b];
        xin[Cn] = nd;
    }
    __syncthreads();

    const float* W; const float* bb;
    if (s == 0)           { W = srcW;  bb = srcB;  }
    else if (s == Sn - 1) { W = depW;  bb = depB;  }
    else                  { W = candW; bb = candB; }

    int c = t;
    float acc0 = bb[c], acc1 = bb[c + 256];
    #pragma unroll 4
    for (int k = 0; k < INDIM; k++) {
        float xv = xin[k];
        acc0 += xv * W[k * Dn + c];
        acc1 += xv * W[k * Dn + c + 256];
    }
    g_x [(size_t)row * Dn + c]       = acc0;
    g_x [(size_t)row * Dn + c + 256] = acc1;
    g_xt[(size_t)row * Dn + c]       = __float2half_rn(acc0);
    g_xt[(size_t)row * Dn + c + 256] = __float2half_rn(acc1);
}

// ============================================================
// feasibility head
// ============================================================
__global__ void feas_kernel(const float* __restrict__ fW,
                            const float* __restrict__ fB,
                            float* __restrict__ out)
{
    int s = blockIdx.x + 1;
    int b = blockIdx.y;
    const float* xr = g_x + (size_t)(b * Sn + s) * Dn;
    int t = threadIdx.x;
    float acc = 0.f;
    #pragma unroll 4
    for (int k = t; k < Dn; k += 128) acc += xr[k] * fW[k];
    __shared__ float red[128];
    red[t] = acc; __syncthreads();
    for (int o = 64; o > 0; o >>= 1) {
        if (t < o) red[t] += red[t + o];
        __syncthreads();
    }
    if (t == 0) out[OUT_FEAS_OFF + b * 510 + (s - 1)] = red[0] + fB[0];
}

// ============================================================
// pointer logits
// ============================================================
__global__ void logits_kernel(const float* __restrict__ pW,
                              const float* __restrict__ pB,
                              float* __restrict__ out)
{
    int s = blockIdx.x + 1;
    int b = blockIdx.y;
    const float* xr = g_x + (size_t)(b * Sn + s) * Dn;
    int t = threadIdx.x;
    float a0 = 0.f, a1 = 0.f;
    #pragma unroll 4
    for (int k = t; k < Dn; k += 128) {
        float xv = xr[k];
        a0 += xv * pW[k * 2 + 0];
        a1 += xv * pW[k * 2 + 1];
    }
    __shared__ float r0[128], r1[128];
    r0[t] = a0; r1[t] = a1; __syncthreads();
    for (int o = 64; o > 0; o >>= 1) {
        if (t < o) { r0[t] += r0[t + o]; r1[t] += r1[t + o]; }
        __syncthreads();
    }
    if (t == 0) {
        out[b * OUT_LOGITS_PER_B + (s - 1)]       = r0[0] + pB[0];
        out[b * OUT_LOGITS_PER_B + 510 + (s - 1)] = r1[0] + pB[1];
    }
}

// ============================================================
// host orchestration
// ============================================================
extern "C" void kernel_launch(void* const* d_in, const int* in_sizes, int n_in,
                              void* d_out, int out_size)
{
    const float* sol   = (const float*)d_in[0];
    const float* cap   = (const float*)d_in[1];
    const float* emb   = (const float*)d_in[2];
    const float* srcW  = (const float*)d_in[3];
    const float* srcB  = (const float*)d_in[4];
    const float* candW = (const float*)d_in[5];
    const float* candB = (const float*)d_in[6];
    const float* depW  = (const float*)d_in[7];
    const float* depB  = (const float*)d_in[8];
    const float* feasW = (const float*)d_in[9];
    const float* feasB = (const float*)d_in[10];
    const float* Wq    = (const float*)d_in[11];
    const float* bq    = (const float*)d_in[12];
    const float* Wk    = (const float*)d_in[13];
    const float* bk    = (const float*)d_in[14];
    const float* Wv    = (const float*)d_in[15];
    const float* bv    = (const float*)d_in[16];
    const float* Wo    = (const float*)d_in[17];
    const float* bo    = (const float*)d_in[18];
    // d_in[19] = s_scale : softmax-shift-invariant, unused
    const float* W1    = (const float*)d_in[20];
    const float* b1    = (const float*)d_in[21];
    const float* W2    = (const float*)d_in[22];
    const float* b2    = (const float*)d_in[23];
    const float* ptrW  = (const float*)d_in[24];
    const float* ptrB  = (const float*)d_in[25];
    float* out = (float*)d_out;
    (void)in_sizes; (void)n_in; (void)out_size;

    float  *px;
    __half *pxt, *pq, *pk, *patt, *pvT, *ph;
    __half *pwqkvT, *pwoT, *pw1T, *pw2T;
    float  *pbqkv;
    cudaGetSymbolAddress((void**)&px,     g_x);
    cudaGetSymbolAddress((void**)&pxt,    g_xt);
    cudaGetSymbolAddress((void**)&pq,     g_q);
    cudaGetSymbolAddress((void**)&pk,     g_k);
    cudaGetSymbolAddress((void**)&patt,   g_att);
    cudaGetSymbolAddress((void**)&pvT,    g_vT);
    cudaGetSymbolAddress((void**)&ph,     g_h);
    cudaGetSymbolAddress((void**)&pwqkvT, g_wqkvT);
    cudaGetSymbolAddress((void**)&pbqkv,  g_bqkv);
    cudaGetSymbolAddress((void**)&pwoT,   g_woT);
    cudaGetSymbolAddress((void**)&pw1T,   g_w1T);
    cudaGetSymbolAddress((void**)&pw2T,   g_w2T);

    const int SM8 = 128 * 4 + 3 * (128 + 128) * 64 * 2;   // 98816
    const int SM4 = 64 * 4 + 3 * (128 + 64) * 64 * 2;     // 73984
    cudaFuncSetAttribute(mma_gemm<8, false, false, true,  false>, cudaFuncAttributeMaxDynamicSharedMemorySize, SM8);
    cudaFuncSetAttribute(mma_gemm<8, true,  false, false, true >, cudaFuncAttributeMaxDynamicSharedMemorySize, SM8);
    cudaFuncSetAttribute(mma_gemm<4, false, true,  false, false>, cudaFuncAttributeMaxDynamicSharedMemorySize, SM4);
    cudaFuncSetAttribute(flash_kernel, cudaFuncAttributeMaxDynamicSharedMemorySize, FLASH_SMEM);

    const size_t DD = (size_t)Dn * Dn;           // 262144
    const size_t DH = (size_t)Dn * HIDn;         // 1048576
    const size_t QKVS = (size_t)1536 * Dn;       // 786432

    // ---- pack weights (fp16): QKV concat [1536,512], others [N,K] ----
    dim3 tb(32, 8);
    transpose_kernel<<<dim3(16, 16, Ln), tb>>>(Wq, pwqkvT, Dn, Dn, QKVS, 0);
    transpose_kernel<<<dim3(16, 16, Ln), tb>>>(Wk, pwqkvT, Dn, Dn, QKVS, DD);
    transpose_kernel<<<dim3(16, 16, Ln), tb>>>(Wv, pwqkvT, Dn, Dn, QKVS, 2 * DD);
    transpose_kernel<<<dim3(16, 16, Ln), tb>>>(Wo, pwoT, Dn, Dn, DD, 0);
    transpose_kernel<<<dim3(64, 16, Ln), tb>>>(W1, pw1T, Dn, HIDn, DH, 0);
    transpose_kernel<<<dim3(16, 64, Ln), tb>>>(W2, pw2T, HIDn, Dn, DH, 0);
    packbias_kernel<<<Ln, 512>>>(bq, bk, bv, pbqkv);

    build_x_kernel<<<Mn, 256>>>(sol, cap, emb, srcW, srcB, candW, candB, depW, depB);

    const dim3 gQKV(12, 32, 1);     // 384 CTAs (BN=128)
    const dim3 gP4 (8, 32, 1);      // 256 CTAs (BN=64)
    const dim3 gFF1(16, 32, 1);     // 512 CTAs
    const dim3 gFl (4, 64, 1);      // 256 CTAs

    for (int i = 0; i < Ln; i++) {
        // ---- fused QKV projection (fp16 outputs; V per-head-transposed) ----
        mma_gemm<8, false, false, true, false><<<gQKV, 128, SM8>>>(
            pxt, Dn,  pwqkvT + i * QKVS, Dn,  pq, Dn,
            pbqkv + i * 1536, nullptr, 1.0f, Dn, pk, pvT, nullptr);

        // ---- flash attention ----
        flash_kernel<<<gFl, 256, FLASH_SMEM>>>();

        // ---- O projection + residual (writes x fp32 + xt fp16) ----
        mma_gemm<4, false, true, false, false><<<gP4, 128, SM4>>>(
            patt, Dn,  pwoT + i * DD, Dn,  px, Dn,
            bo + i * Dn, px, 1.0f, Dn, nullptr, nullptr, pxt);

        if (i == 0)
            feas_kernel<<<dim3(510, Bn), 128>>>(feasW, feasB, out);

        // ---- FFN (h stored fp16) ----
        mma_gemm<8, true, false, false, true><<<gFF1, 128, SM8>>>(
            pxt, Dn,  pw1T + i * DH, Dn,  ph, HIDn,
            b1 + i * HIDn, nullptr, 1.0f, Dn, nullptr, nullptr, nullptr);
        mma_gemm<4, false, true, false, false><<<gP4, 128, SM4>>>(
            ph, HIDn,  pw2T + i * DH, HIDn,  px, Dn,
            b2 + i * Dn, px, 1.0f, HIDn, nullptr, nullptr, pxt);
    }

    logits_kernel<<<dim3(510, Bn), 128>>>(ptrW, ptrB, out);
}

// round 9
// speedup vs baseline: 6.9782x; 1.0882x over previous
#include <cuda_runtime.h>
#include <cuda_fp16.h>
#include <cstdint>

// ---------------- problem constants ----------------
#define Bn   8
#define Sn   512
#define Ln   6
#define Dn   512
#define Hn   8
#define HDn  64
#define HIDn 2048
#define Cn   256
#define INDIM 257
#define Mn   (Bn * Sn)          // 4096 rows

#define OUT_LOGITS_PER_B 1020   // 2 * 510
#define OUT_FEAS_OFF     (Bn * OUT_LOGITS_PER_B)   // 8160

// ---------------- scratch (device globals; no allocation) ----------------
__device__ float  g_x  [Mn * Dn];            // residual stream (fp32)
__device__ __half g_xt [Mn * Dn];            // residual stream (fp16)
__device__ __half g_q  [Mn * Dn];            // Q (fp16)
__device__ __half g_k  [Mn * Dn];            // K (fp16)
__device__ __half g_att[Mn * Dn];            // attention out (fp16)
__device__ __half g_vT [Mn * Dn];            // V^T per head [b,h,e,s] (fp16)
__device__ __half g_h  [Mn * HIDn];          // FFN hidden (fp16)
// transposed weights ([N,K] K-major, fp16)
__device__ __half g_wqkvT[Ln * 1536 * Dn];   // concat QKV [1536,512] per layer
__device__ float  g_bqkv [Ln * 1536];
__device__ __half g_woT[Ln * Dn * Dn];
__device__ __half g_w1T[Ln * Dn * HIDn];
__device__ __half g_w2T[Ln * HIDn * Dn];

// ============================================================
// portable PTX helpers
// ============================================================
__device__ __forceinline__ uint32_t su32(const void* p) {
    uint32_t a;
    asm("{ .reg .u64 t; cvta.to.shared.u64 t, %1; cvt.u32.u64 %0, t; }" : "=r"(a) : "l"(p));
    return a;
}
__device__ __forceinline__ void cp_async16(uint32_t s, const void* g) {
    asm volatile("cp.async.cg.shared.global [%0], [%1], 16;" :: "r"(s), "l"(g));
}
#define CP_COMMIT() asm volatile("cp.async.commit_group;" ::: "memory")
#define CP_WAIT(n)  asm volatile("cp.async.wait_group %0;" :: "n"(n) : "memory")

// fp16 mma: D(f32) += A(f16) B(f16)^T ; A=4 regs (8 halves), B=2 regs (4 halves)
#define MMA16(dd, af, b0, b1) \
    asm volatile("mma.sync.aligned.m16n8k16.row.col.f32.f16.f16.f32 " \
        "{%0,%1,%2,%3}, {%4,%5,%6,%7}, {%8,%9}, {%0,%1,%2,%3};" \
        : "+f"((dd)[0]), "+f"((dd)[1]), "+f"((dd)[2]), "+f"((dd)[3]) \
        : "r"((af)[0]), "r"((af)[1]), "r"((af)[2]), "r"((af)[3]), "r"(b0), "r"(b1))

// ldmatrix x4: each lane supplies the address of one 16B row of an 8x8 b16 tile
#define LDSM4(r0, r1, r2, r3, addr) \
    asm volatile("ldmatrix.sync.aligned.m8n8.x4.shared.b16 {%0,%1,%2,%3}, [%4];" \
        : "=r"(r0), "=r"(r1), "=r"(r2), "=r"(r3) : "r"(addr))

// half-element index in a [row][64-half] tile (128B rows, 16B-chunk XOR swizzle)
__device__ __forceinline__ int swzh(int row, int k) {
    return (row << 6) + ((((k >> 3) ^ row) & 7) << 3) + (k & 7);
}
__device__ __forceinline__ uint32_t ldsu(const __half* p) {
    return *(const uint32_t*)p;
}

// ============================================================
// fp16 mma.sync GEMM: C = scale*(A B^T) (+bias, +Res, ReLU)
// CTA 128 x (NT*16); BK=64 halves; 3-stage cp.async; 128 threads; 2 CTAs/SM.
// ldmatrix.x4 fragment loads. QKV: epilogue routes q/k/vT (fp16).
// TOUT: C is fp16. Ct: fp16 shadow of C.
// ============================================================
template<int NT, bool RELU, bool RES, bool QKV, bool TOUT>
__global__ __launch_bounds__(128, 2) void mma_gemm(
    const __half* __restrict__ A, int lda,
    const __half* __restrict__ B, int ldb,
    void* __restrict__ Cp, int ldc,
    const float* __restrict__ bias, const float* __restrict__ Res,
    float scale, int K,
    __half* __restrict__ Ck, __half* __restrict__ Cv, __half* __restrict__ Ct)
{
    constexpr int BM = 128, BK = 64;
    constexpr int BN = NT * 16;
    constexpr int NSTAGE = 3;
    constexpr int STAGE_H = (BM + BN) * BK;      // halves per stage

    extern __shared__ float smem[];
    float* sbias = smem;
    __half* sdata = (__half*)(smem + BN);

    const int t = threadIdx.x;
    const int m0 = blockIdx.y * BM;
    const int n0 = blockIdx.x * BN;

    if (bias != nullptr && t < BN) sbias[t] = bias[n0 + t];

    auto load_stage = [&](int st, int k0) {
        __half* sa = sdata + (st % NSTAGE) * STAGE_H;
        __half* sb = sa + BM * BK;
        #pragma unroll
        for (int i = 0; i < 8; i++) {             // A: 128 rows x 8 chunks
            int j = t + 128 * i;
            int m = j >> 3, f = j & 7;
            uint32_t dst = su32(&sa[(m << 6) + (((f ^ m) & 7) << 3)]);
            cp_async16(dst, A + (size_t)(m0 + m) * lda + k0 + (f << 3));
        }
        #pragma unroll
        for (int i = 0; i < NT; i++) {            // B: BN rows x 8 chunks
            int j = t + 128 * i;
            int n = j >> 3, f = j & 7;
            uint32_t dst = su32(&sb[(n << 6) + (((f ^ n) & 7) << 3)]);
            cp_async16(dst, B + (size_t)(n0 + n) * ldb + k0 + (f << 3));
        }
        CP_COMMIT();
    };

    const int nst = K / BK;
    load_stage(0, 0);
    load_stage(1, BK);

    const int lane = t & 31, w = t >> 5;
    const int wm = w >> 1, wn = w & 1;
    const int g = lane >> 2, t4 = lane & 3;
    // ldmatrix lane->address constants
    const int jj  = lane >> 3;                   // 0..3 (matrix id)
    const int rA  = ((jj & 1) << 3) + (lane & 7);
    const int kA  = (jj >> 1) << 3;
    const int rB  = lane & 7;
    const int ntO = jj >> 1;                     // which nt of the pair
    const int kB_ = (jj & 1) << 3;

    float d[4][NT][4] = {};

    for (int s = 0; s < nst; s++) {
        if (s < nst - 1) { CP_WAIT(1); } else { CP_WAIT(0); }
        __syncthreads();
        if (s + 2 < nst) load_stage(s + 2, (s + 2) * BK);

        uint32_t sa_u = su32(sdata + (s % NSTAGE) * STAGE_H);
        uint32_t sb_u = sa_u + BM * BK * 2;
        #pragma unroll
        for (int k16 = 0; k16 < 4; k16++) {
            const int kb = k16 << 4;
            uint32_t af[4][4];
            #pragma unroll
            for (int mt = 0; mt < 4; mt++) {
                int r = wm * 64 + mt * 16 + rA;
                LDSM4(af[mt][0], af[mt][1], af[mt][2], af[mt][3],
                      sa_u + (swzh(r, kb + kA) << 1));
            }
            uint32_t bf[NT][2];
            #pragma unroll
            for (int np = 0; np < NT / 2; np++) {
                int n = wn * NT * 8 + ((np * 2 + ntO) << 3) + rB;
                LDSM4(bf[np * 2][0], bf[np * 2][1], bf[np * 2 + 1][0], bf[np * 2 + 1][1],
                      sb_u + (swzh(n, kb + kB_) << 1));
            }
            #pragma unroll
            for (int nt = 0; nt < NT; nt++)
                #pragma unroll
                for (int mt = 0; mt < 4; mt++) MMA16(d[mt][nt], af[mt], bf[nt][0], bf[nt][1]);
        }
    }

    // ---------------- epilogue ----------------
    const int colw = wn * NT * 8;
    #pragma unroll
    for (int mt = 0; mt < 4; mt++) {
        #pragma unroll
        for (int h2 = 0; h2 < 2; h2++) {
            const int m = m0 + wm * 64 + mt * 16 + g + h2 * 8;
            if (QKV) {
                const int region = n0 >> 9;       // 0=Q, 1=K, 2=V
                const int nb = n0 & 511;
                if (region < 2) {
                    __half* crow = (region == 0 ? (__half*)Cp : Ck) + (size_t)m * 512 + nb;
                    #pragma unroll
                    for (int nt = 0; nt < NT; nt++) {
                        int cl = colw + nt * 8 + 2 * t4;
                        float v0 = d[mt][nt][h2 * 2]     + sbias[cl];
                        float v1 = d[mt][nt][h2 * 2 + 1] + sbias[cl + 1];
                        *(__half2*)(crow + cl) = __floats2half2_rn(v0, v1);
                    }
                } else {
                    #pragma unroll
                    for (int nt = 0; nt < NT; nt++) {
                        int cl = colw + nt * 8 + 2 * t4;
                        float v0 = d[mt][nt][h2 * 2]     + sbias[cl];
                        float v1 = d[mt][nt][h2 * 2 + 1] + sbias[cl + 1];
                        int gc = nb + cl;
                        int hh = gc >> 6, e = gc & 63;
                        size_t base = ((size_t)((m >> 9) * Hn + hh) * 64 + e) * 512
                                      + (size_t)(m & 511);
                        Cv[base]       = __float2half_rn(v0);
                        Cv[base + 512] = __float2half_rn(v1);
                    }
                }
            } else if (TOUT) {
                __half* crow = (__half*)Cp + (size_t)m * ldc + n0;
                #pragma unroll
                for (int nt = 0; nt < NT; nt++) {
                    int cl = colw + nt * 8 + 2 * t4;
                    float v0 = d[mt][nt][h2 * 2]     + sbias[cl];
                    float v1 = d[mt][nt][h2 * 2 + 1] + sbias[cl + 1];
                    if (RELU) { v0 = fmaxf(v0, 0.f); v1 = fmaxf(v1, 0.f); }
                    *(__half2*)(crow + cl) = __floats2half2_rn(v0, v1);
                }
            } else {
                float* crow = (float*)Cp + (size_t)m * ldc + n0;
                __half* trow = (Ct != nullptr) ? (Ct + (size_t)m * ldc + n0) : nullptr;
                const float* rrow = RES ? (Res + (size_t)m * ldc + n0) : nullptr;
                #pragma unroll
                for (int nt = 0; nt < NT; nt++) {
                    int cl = colw + nt * 8 + 2 * t4;
                    float v0 = d[mt][nt][h2 * 2]     * scale;
                    float v1 = d[mt][nt][h2 * 2 + 1] * scale;
                    if (bias != nullptr) { v0 += sbias[cl]; v1 += sbias[cl + 1]; }
                    if (RELU) { v0 = fmaxf(v0, 0.f); v1 = fmaxf(v1, 0.f); }
                    if (RES) {
                        float2 r = *(const float2*)(rrow + cl);
                        v0 += r.x; v1 += r.y;
                    }
                    *(float2*)(crow + cl) = make_float2(v0, v1);
                    if (Ct != nullptr)
                        *(__half2*)(trow + cl) = __floats2half2_rn(v0, v1);
                }
            }
        }
    }
}

// ============================================================
// flash attention (fp16 operands, fp32 accum/softmax), ldmatrix frag loads
// per (b,h,qtile 128); 256 threads; smem 96KB.
// ============================================================
#define FLASH_SMEM 98304
#define NEG_INF (-1e30f)

__global__ __launch_bounds__(256) void flash_kernel()
{
    extern __shared__ __half smh[];
    __half* Ps = smh;                          // 16384 halves

    const int t = threadIdx.x;
    const int lane = t & 31, w = t >> 5;
    const int g = lane >> 2, t4 = lane & 3;
    const int jj  = lane >> 3;
    const int rA  = ((jj & 1) << 3) + (lane & 7);
    const int kA  = (jj >> 1) << 3;
    const int rB  = lane & 7;
    const int ntO = jj >> 1;
    const int kB_ = (jj & 1) << 3;
    const int q0 = blockIdx.x * 128;
    const int b = blockIdx.y >> 3, h = blockIdx.y & 7;
    const int r0 = w * 16;

    const __half* qg = g_q  + (size_t)(b * Sn + q0) * Dn + h * HDn;
    const __half* kg = g_k  + (size_t)(b * Sn) * Dn + h * HDn;
    const __half* vg = g_vT + (size_t)(b * Hn + h) * HDn * Sn;

    // ---- stage Q into Ps chunk0: [128 q][64 e] ----
    #pragma unroll
    for (int i = 0; i < 4; i++) {
        int j = t + 256 * i;
        int r = j >> 3, f = j & 7;
        uint32_t dst = su32(&Ps[(r << 6) + (((f ^ r) & 7) << 3)]);
        cp_async16(dst, qg + (size_t)r * Dn + (f << 3));
    }
    CP_COMMIT();

    auto load_kv = [&](int tile, int st) {
        __half* kb = smh + 16384 + st * 16384;
        __half* vb = kb + 8192;
        #pragma unroll
        for (int i = 0; i < 4; i++) {          // K tile [128 s][64 e]
            int j = t + 256 * i;
            int r = j >> 3, f = j & 7;
            uint32_t dst = su32(&kb[(r << 6) + (((f ^ r) & 7) << 3)]);
            cp_async16(dst, kg + (size_t)(tile * 128 + r) * Dn + (f << 3));
        }
        #pragma unroll
        for (int i = 0; i < 4; i++) {          // V^T tile [64 e][128 s] -> 2 chunks
            int j = t + 256 * i;
            int e = j >> 4, f = j & 15;
            int ss = f >> 3, fc = f & 7;
            uint32_t dst = su32(&vb[ss * 4096 + (e << 6) + (((fc ^ e) & 7) << 3)]);
            cp_async16(dst, vg + (size_t)e * Sn + tile * 128 + (f << 3));
        }
        CP_COMMIT();
    };
    load_kv(0, 0);
    load_kv(1, 1);

    // ---- Q fragments (held in regs) ----
    CP_WAIT(2);
    __syncthreads();
    uint32_t qf[4][4];
    {
        uint32_t ps_u = su32(Ps);
        #pragma unroll
        for (int k16 = 0; k16 < 4; k16++) {
            const int kb = k16 << 4;
            LDSM4(qf[k16][0], qf[k16][1], qf[k16][2], qf[k16][3],
                  ps_u + (swzh(r0 + rA, kb + kA) << 1));
        }
    }
    __syncthreads();

    float m0 = NEG_INF, m1 = NEG_INF, l0 = 0.f, l1 = 0.f;
    float o[8][4] = {};
    const uint32_t ps_u = su32(Ps);

    for (int tile = 0; tile < 4; tile++) {
        if (tile < 3) { CP_WAIT(1); } else { CP_WAIT(0); }
        __syncthreads();
        const __half* kbp = smh + 16384 + (tile & 1) * 16384;
        const uint32_t kb_u = su32(kbp);
        const uint32_t vb_u = kb_u + 8192 * 2;

        // ---- S = Q K^T ----
        float s[16][4];
        #pragma unroll
        for (int nt = 0; nt < 16; nt++)
            #pragma unroll
            for (int j = 0; j < 4; j++) s[nt][j] = 0.f;
        #pragma unroll
        for (int k16 = 0; k16 < 4; k16++) {
            const int kk = k16 << 4;
            #pragma unroll
            for (int np = 0; np < 8; np++) {
                uint32_t b00, b01, b10, b11;
                int n = ((np * 2 + ntO) << 3) + rB;
                LDSM4(b00, b01, b10, b11, kb_u + (swzh(n, kk + kB_) << 1));
                MMA16(s[np * 2],     qf[k16], b00, b01);
                MMA16(s[np * 2 + 1], qf[k16], b10, b11);
            }
        }

        // ---- online softmax update ----
        float rm0 = NEG_INF, rm1 = NEG_INF;
        #pragma unroll
        for (int nt = 0; nt < 16; nt++) {
            s[nt][0] *= 0.125f; s[nt][1] *= 0.125f;
            s[nt][2] *= 0.125f; s[nt][3] *= 0.125f;
            rm0 = fmaxf(rm0, fmaxf(s[nt][0], s[nt][1]));
            rm1 = fmaxf(rm1, fmaxf(s[nt][2], s[nt][3]));
        }
        rm0 = fmaxf(rm0, __shfl_xor_sync(0xFFFFFFFF, rm0, 1));
        rm0 = fmaxf(rm0, __shfl_xor_sync(0xFFFFFFFF, rm0, 2));
        rm1 = fmaxf(rm1, __shfl_xor_sync(0xFFFFFFFF, rm1, 1));
        rm1 = fmaxf(rm1, __shfl_xor_sync(0xFFFFFFFF, rm1, 2));
        float mn0 = fmaxf(m0, rm0), mn1 = fmaxf(m1, rm1);
        float a0 = __expf(m0 - mn0), a1 = __expf(m1 - mn1);
        m0 = mn0; m1 = mn1;

        float rs0 = 0.f, rs1 = 0.f;
        #pragma unroll
        for (int nt = 0; nt < 16; nt++) {
            float p0 = __expf(s[nt][0] - m0);
            float p1 = __expf(s[nt][1] - m0);
            float p2 = __expf(s[nt][2] - m1);
            float p3 = __expf(s[nt][3] - m1);
            rs0 += p0 + p1; rs1 += p2 + p3;
            int col = nt * 8 + 2 * t4;
            int ch = col >> 6, kc = col & 63;
            *(__half2*)&Ps[ch * 8192 + swzh(r0 + g, kc)]     = __floats2half2_rn(p0, p1);
            *(__half2*)&Ps[ch * 8192 + swzh(r0 + g + 8, kc)] = __floats2half2_rn(p2, p3);
        }
        rs0 += __shfl_xor_sync(0xFFFFFFFF, rs0, 1);
        rs0 += __shfl_xor_sync(0xFFFFFFFF, rs0, 2);
        rs1 += __shfl_xor_sync(0xFFFFFFFF, rs1, 1);
        rs1 += __shfl_xor_sync(0xFFFFFFFF, rs1, 2);
        l0 = l0 * a0 + rs0;
        l1 = l1 * a1 + rs1;
        #pragma unroll
        for (int nt = 0; nt < 8; nt++) {
            o[nt][0] *= a0; o[nt][1] *= a0;
            o[nt][2] *= a1; o[nt][3] *= a1;
        }
        __syncwarp();

        // ---- O += P @ V^T ----
        #pragma unroll
        for (int ks = 0; ks < 8; ks++) {
            const int ch = ks >> 2, kk = (ks << 4) & 63;
            uint32_t af[4];
            LDSM4(af[0], af[1], af[2], af[3],
                  ps_u + ch * 16384 + (swzh(r0 + rA, kk + kA) << 1));
            #pragma unroll
            for (int np = 0; np < 4; np++) {
                uint32_t b00, b01, b10, b11;
                int n = ((np * 2 + ntO) << 3) + rB;
                LDSM4(b00, b01, b10, b11, vb_u + ch * 8192 + (swzh(n, kk + kB_) << 1));
                MMA16(o[np * 2],     af, b00, b01);
                MMA16(o[np * 2 + 1], af, b10, b11);
            }
        }
        __syncthreads();
        if (tile + 2 < 4) load_kv(tile + 2, tile & 1);
    }

    // ---- epilogue: O / l -> g_att (fp16) ----
    float inv0 = 1.0f / l0, inv1 = 1.0f / l1;
    __half* orow0 = g_att + (size_t)(b * Sn + q0 + r0 + g) * Dn + h * HDn;
    __half* orow1 = orow0 + 8 * Dn;
    #pragma unroll
    for (int nt = 0; nt < 8; nt++) {
        int col = nt * 8 + 2 * t4;
        *(__half2*)(orow0 + col) = __floats2half2_rn(o[nt][0] * inv0, o[nt][1] * inv0);
        *(__half2*)(orow1 + col) = __floats2half2_rn(o[nt][2] * inv1, o[nt][3] * inv1);
    }
}

// ============================================================
// weight transpose -> fp16: dst[zdst + c*R + r] = h(src[z][r][c])
// ============================================================
__global__ void transpose_kernel(const float* __restrict__ src, __half* __restrict__ dst,
                                 int R, int C, size_t zstride, size_t doff)
{
    __shared__ float tile[32][33];
    size_t zsrc = (size_t)blockIdx.z * R * C;
    size_t zdst = (size_t)blockIdx.z * zstride + doff;
    int c0 = blockIdx.x * 32, r0 = blockIdx.y * 32;
    int tx = threadIdx.x, ty = threadIdx.y;       // 32 x 8
    #pragma unroll
    for (int j = 0; j < 32; j += 8)
        tile[ty + j][tx] = src[zsrc + (size_t)(r0 + ty + j) * C + c0 + tx];
    __syncthreads();
    #pragma unroll
    for (int j = 0; j < 32; j += 8)
        dst[zdst + (size_t)(c0 + ty + j) * R + r0 + tx] = __float2half_rn(tile[tx][ty + j]);
}

__global__ void packbias_kernel(const float* __restrict__ bq, const float* __restrict__ bk,
                                const float* __restrict__ bv, float* __restrict__ dst)
{
    int i = blockIdx.x, t = threadIdx.x;   // Ln x 512
    dst[i * 1536 + t]        = bq[i * 512 + t];
    dst[i * 1536 + 512 + t]  = bk[i * 512 + t];
    dst[i * 1536 + 1024 + t] = bv[i * 512 + t];
}

// ============================================================
// build x = class_proj(concat(embed[idx], nd)); writes fp32 + fp16 shadow
// ============================================================
__global__ void build_x_kernel(const float* __restrict__ sol,
                               const float* __restrict__ cap,
                               const float* __restrict__ emb,
                               const float* __restrict__ srcW, const float* __restrict__ srcB,
                               const float* __restrict__ candW, const float* __restrict__ candB,
                               const float* __restrict__ depW, const float* __restrict__ depB)
{
    int row = blockIdx.x;
    int b = row / Sn, s = row % Sn;
    __shared__ float xin[INDIM];
    int t = threadIdx.x;

    int idx = (int)sol[(size_t)row * 4 + 0];
    xin[t] = emb[(size_t)idx * Cn + t];
    if (t == 0) {
        float rem = sol[(size_t)(b * Sn) * 4 + 3];
        float nd = (s == 0) ? 0.0f : 2.0f * (sol[(size_t)row * 4 + 2] - rem) / cap[b];
        xin[Cn] = nd;
    }
    __syncthreads();

    const float* W; const float* bb;
    if (s == 0)           { W = srcW;  bb = srcB;  }
    else if (s == Sn - 1) { W = depW;  bb = depB;  }
    else                  { W = candW; bb = candB; }

    int c = t;
    float acc0 = bb[c], acc1 = bb[c + 256];
    #pragma unroll 4
    for (int k = 0; k < INDIM; k++) {
        float xv = xin[k];
        acc0 += xv * W[k * Dn + c];
        acc1 += xv * W[k * Dn + c + 256];
    }
    g_x [(size_t)row * Dn + c]       = acc0;
    g_x [(size_t)row * Dn + c + 256] = acc1;
    g_xt[(size_t)row * Dn + c]       = __float2half_rn(acc0);
    g_xt[(size_t)row * Dn + c + 256] = __float2half_rn(acc1);
}

// ============================================================
// feasibility head
// ============================================================
__global__ void feas_kernel(const float* __restrict__ fW,
                            const float* __restrict__ fB,
                            float* __restrict__ out)
{
    int s = blockIdx.x + 1;
    int b = blockIdx.y;
    const float* xr = g_x + (size_t)(b * Sn + s) * Dn;
    int t = threadIdx.x;
    float acc = 0.f;
    #pragma unroll 4
    for (int k = t; k < Dn; k += 128) acc += xr[k] * fW[k];
    __shared__ float red[128];
    red[t] = acc; __syncthreads();
    for (int o = 64; o > 0; o >>= 1) {
        if (t < o) red[t] += red[t + o];
        __syncthreads();
    }
    if (t == 0) out[OUT_FEAS_OFF + b * 510 + (s - 1)] = red[0] + fB[0];
}

// ============================================================
// pointer logits
// ============================================================
__global__ void logits_kernel(const float* __restrict__ pW,
                              const float* __restrict__ pB,
                              float* __restrict__ out)
{
    int s = blockIdx.x + 1;
    int b = blockIdx.y;
    const float* xr = g_x + (size_t)(b * Sn + s) * Dn;
    int t = threadIdx.x;
    float a0 = 0.f, a1 = 0.f;
    #pragma unroll 4
    for (int k = t; k < Dn; k += 128) {
        float xv = xr[k];
        a0 += xv * pW[k * 2 + 0];
        a1 += xv * pW[k * 2 + 1];
    }
    __shared__ float r0[128], r1[128];
    r0[t] = a0; r1[t] = a1; __syncthreads();
    for (int o = 64; o > 0; o >>= 1) {
        if (t < o) { r0[t] += r0[t + o]; r1[t] += r1[t + o]; }
        __syncthreads();
    }
    if (t == 0) {
        out[b * OUT_LOGITS_PER_B + (s - 1)]       = r0[0] + pB[0];
        out[b * OUT_LOGITS_PER_B + 510 + (s - 1)] = r1[0] + pB[1];
    }
}

// ============================================================
// host orchestration
// ============================================================
extern "C" void kernel_launch(void* const* d_in, const int* in_sizes, int n_in,
                              void* d_out, int out_size)
{
    const float* sol   = (const float*)d_in[0];
    const float* cap   = (const float*)d_in[1];
    const float* emb   = (const float*)d_in[2];
    const float* srcW  = (const float*)d_in[3];
    const float* srcB  = (const float*)d_in[4];
    const float* candW = (const float*)d_in[5];
    const float* candB = (const float*)d_in[6];
    const float* depW  = (const float*)d_in[7];
    const float* depB  = (const float*)d_in[8];
    const float* feasW = (const float*)d_in[9];
    const float* feasB = (const float*)d_in[10];
    const float* Wq    = (const float*)d_in[11];
    const float* bq    = (const float*)d_in[12];
    const float* Wk    = (const float*)d_in[13];
    const float* bk    = (const float*)d_in[14];
    const float* Wv    = (const float*)d_in[15];
    const float* bv    = (const float*)d_in[16];
    const float* Wo    = (const float*)d_in[17];
    const float* bo    = (const float*)d_in[18];
    // d_in[19] = s_scale : softmax-shift-invariant, unused
    const float* W1    = (const float*)d_in[20];
    const float* b1    = (const float*)d_in[21];
    const float* W2    = (const float*)d_in[22];
    const float* b2    = (const float*)d_in[23];
    const float* ptrW  = (const float*)d_in[24];
    const float* ptrB  = (const float*)d_in[25];
    float* out = (float*)d_out;
    (void)in_sizes; (void)n_in; (void)out_size;

    float  *px;
    __half *pxt, *pq, *pk, *patt, *pvT, *ph;
    __half *pwqkvT, *pwoT, *pw1T, *pw2T;
    float  *pbqkv;
    cudaGetSymbolAddress((void**)&px,     g_x);
    cudaGetSymbolAddress((void**)&pxt,    g_xt);
    cudaGetSymbolAddress((void**)&pq,     g_q);
    cudaGetSymbolAddress((void**)&pk,     g_k);
    cudaGetSymbolAddress((void**)&patt,   g_att);
    cudaGetSymbolAddress((void**)&pvT,    g_vT);
    cudaGetSymbolAddress((void**)&ph,     g_h);
    cudaGetSymbolAddress((void**)&pwqkvT, g_wqkvT);
    cudaGetSymbolAddress((void**)&pbqkv,  g_bqkv);
    cudaGetSymbolAddress((void**)&pwoT,   g_woT);
    cudaGetSymbolAddress((void**)&pw1T,   g_w1T);
    cudaGetSymbolAddress((void**)&pw2T,   g_w2T);

    const int SM8 = 128 * 4 + 3 * (128 + 128) * 64 * 2;   // 98816
    const int SM4 = 64 * 4 + 3 * (128 + 64) * 64 * 2;     // 73984
    cudaFuncSetAttribute(mma_gemm<8, false, false, true,  false>, cudaFuncAttributeMaxDynamicSharedMemorySize, SM8);
    cudaFuncSetAttribute(mma_gemm<8, true,  false, false, true >, cudaFuncAttributeMaxDynamicSharedMemorySize, SM8);
    cudaFuncSetAttribute(mma_gemm<4, false, true,  false, false>, cudaFuncAttributeMaxDynamicSharedMemorySize, SM4);
    cudaFuncSetAttribute(flash_kernel, cudaFuncAttributeMaxDynamicSharedMemorySize, FLASH_SMEM);

    const size_t DD = (size_t)Dn * Dn;           // 262144
    const size_t DH = (size_t)Dn * HIDn;         // 1048576
    const size_t QKVS = (size_t)1536 * Dn;       // 786432

    // ---- pack weights (fp16): QKV concat [1536,512], others [N,K] ----
    dim3 tb(32, 8);
    transpose_kernel<<<dim3(16, 16, Ln), tb>>>(Wq, pwqkvT, Dn, Dn, QKVS, 0);
    transpose_kernel<<<dim3(16, 16, Ln), tb>>>(Wk, pwqkvT, Dn, Dn, QKVS, DD);
    transpose_kernel<<<dim3(16, 16, Ln), tb>>>(Wv, pwqkvT, Dn, Dn, QKVS, 2 * DD);
    transpose_kernel<<<dim3(16, 16, Ln), tb>>>(Wo, pwoT, Dn, Dn, DD, 0);
    transpose_kernel<<<dim3(64, 16, Ln), tb>>>(W1, pw1T, Dn, HIDn, DH, 0);
    transpose_kernel<<<dim3(16, 64, Ln), tb>>>(W2, pw2T, HIDn, Dn, DH, 0);
    packbias_kernel<<<Ln, 512>>>(bq, bk, bv, pbqkv);

    build_x_kernel<<<Mn, 256>>>(sol, cap, emb, srcW, srcB, candW, candB, depW, depB);

    const dim3 gQKV(12, 32, 1);     // 384 CTAs (BN=128)
    const dim3 gP4 (8, 32, 1);      // 256 CTAs (BN=64)
    const dim3 gFF1(16, 32, 1);     // 512 CTAs
    const dim3 gFl (4, 64, 1);      // 256 CTAs

    for (int i = 0; i < Ln; i++) {
        // ---- fused QKV projection (fp16 outputs; V per-head-transposed) ----
        mma_gemm<8, false, false, true, false><<<gQKV, 128, SM8>>>(
            pxt, Dn,  pwqkvT + i * QKVS, Dn,  pq, Dn,
            pbqkv + i * 1536, nullptr, 1.0f, Dn, pk, pvT, nullptr);

        // ---- flash attention ----
        flash_kernel<<<gFl, 256, FLASH_SMEM>>>();

        // ---- O projection + residual (writes x fp32 + xt fp16) ----
        mma_gemm<4, false, true, false, false><<<gP4, 128, SM4>>>(
            patt, Dn,  pwoT + i * DD, Dn,  px, Dn,
            bo + i * Dn, px, 1.0f, Dn, nullptr, nullptr, pxt);

        if (i == 0)
            feas_kernel<<<dim3(510, Bn), 128>>>(feasW, feasB, out);

        // ---- FFN (h stored fp16) ----
        mma_gemm<8, true, false, false, true><<<gFF1, 128, SM8>>>(
            pxt, Dn,  pw1T + i * DH, Dn,  ph, HIDn,
            b1 + i * HIDn, nullptr, 1.0f, Dn, nullptr, nullptr, nullptr);
        mma_gemm<4, false, true, false, false><<<gP4, 128, SM4>>>(
            ph, HIDn,  pw2T + i * DH, HIDn,  px, Dn,
            b2 + i * Dn, px, 1.0f, HIDn, nullptr, nullptr, pxt);
    }

    logits_kernel<<<dim3(510, Bn), 128>>>(ptrW, ptrB, out);
}